// round 3
// baseline (speedup 1.0000x reference)
#include <cuda_runtime.h>
#include <math.h>

#define SEQ   2048
#define BATCH 2
#define EMB   1024
#define NH    16
#define HD    64
#define QKVN  (3*EMB)       // 3072
#define ROWS  (BATCH*SEQ)   // 4096
#define AT_PAD 68
#define ATT_SMEM (4*64*AT_PAD*4)   // 69632 bytes

__device__ float g_qkv[ROWS * QKVN];   // [row][3*1024] : q|k|v each [h][d]
__device__ float g_attn[ROWS * EMB];   // [b][s][h][d]

// ---------------- SGEMM: 128x128x16 tile, 256 threads, 8x8 per thread ----------------
__device__ __forceinline__ void sgemm_body(const float* __restrict__ A,
                                           const float* __restrict__ B,
                                           float* __restrict__ C,
                                           int M, int N, int K) {
    __shared__ float As[16][128];   // transposed A tile: [k][m]
    __shared__ float Bs[16][128];   // [k][n]
    const int tid = threadIdx.x;
    const int tx  = tid & 15;
    const int ty  = tid >> 4;
    const int m0  = blockIdx.y * 128;
    const int n0  = blockIdx.x * 128;

    float acc[8][8];
#pragma unroll
    for (int i = 0; i < 8; i++)
#pragma unroll
        for (int j = 0; j < 8; j++) acc[i][j] = 0.f;

    for (int k0 = 0; k0 < K; k0 += 16) {
#pragma unroll
        for (int l = 0; l < 2; l++) {
            int i4  = tid + l * 256;          // 0..511 float4s
            int row = i4 >> 2;                // 0..127
            int kc  = (i4 & 3) << 2;          // 0,4,8,12
            float4 a = *(const float4*)&A[(size_t)(m0 + row) * K + k0 + kc];
            As[kc+0][row] = a.x; As[kc+1][row] = a.y;
            As[kc+2][row] = a.z; As[kc+3][row] = a.w;
        }
#pragma unroll
        for (int l = 0; l < 2; l++) {
            int i4  = tid + l * 256;          // 0..511
            int row = i4 >> 5;                // 0..15
            int col = (i4 & 31) << 2;         // 0..124
            *(float4*)&Bs[row][col] = *(const float4*)&B[(size_t)(k0 + row) * N + n0 + col];
        }
        __syncthreads();
#pragma unroll
        for (int k = 0; k < 16; k++) {
            float4 a0 = *(const float4*)&As[k][ty*4];
            float4 a1 = *(const float4*)&As[k][64 + ty*4];
            float4 b0 = *(const float4*)&Bs[k][tx*4];
            float4 b1 = *(const float4*)&Bs[k][64 + tx*4];
            float ra[8] = {a0.x,a0.y,a0.z,a0.w,a1.x,a1.y,a1.z,a1.w};
            float rb[8] = {b0.x,b0.y,b0.z,b0.w,b1.x,b1.y,b1.z,b1.w};
#pragma unroll
            for (int i = 0; i < 8; i++)
#pragma unroll
                for (int j = 0; j < 8; j++)
                    acc[i][j] = fmaf(ra[i], rb[j], acc[i][j]);
        }
        __syncthreads();
    }
#pragma unroll
    for (int i = 0; i < 8; i++) {
        int m = m0 + ((i < 4) ? (ty*4 + i) : (64 + ty*4 + (i - 4)));
#pragma unroll
        for (int jh = 0; jh < 2; jh++) {
            float4 v = make_float4(acc[i][jh*4+0], acc[i][jh*4+1],
                                   acc[i][jh*4+2], acc[i][jh*4+3]);
            *(float4*)&C[(size_t)m * N + n0 + jh*64 + tx*4] = v;
        }
    }
}

__global__ __launch_bounds__(256) void qkv_gemm_kernel(const float* __restrict__ x,
                                                       const float* __restrict__ Wqkv) {
    sgemm_body(x, Wqkv, g_qkv, ROWS, QKVN, EMB);
}

__global__ __launch_bounds__(256) void out_gemm_kernel(const float* __restrict__ Wout,
                                                       float* __restrict__ out) {
    sgemm_body(g_attn, Wout, out, ROWS, EMB, EMB);
}

// ---------------- RoPE (in place on q and k halves of g_qkv; q pre-scaled) ----------------
__global__ void rope_kernel() {
    int idx = blockIdx.x * blockDim.x + threadIdx.x;
    // idx = ((row*2 + which)*16 + h)*32 + i
    int i     = idx & 31;
    int h     = (idx >> 5) & 15;
    int which = (idx >> 9) & 1;          // 0 = q, 1 = k
    int row   = idx >> 10;               // 0..4095
    if (row >= ROWS) return;
    int s = row & (SEQ - 1);
    float freq = powf(10000.f, -(float)(2*i) / 64.f);
    float ang  = (float)s * freq;
    float sv, cv;
    sincosf(ang, &sv, &cv);
    float* p = &g_qkv[(size_t)row * QKVN + which * EMB + h * HD + 2*i];
    float x1 = p[0], x2 = p[1];
    float o1 = x1 * cv - x2 * sv;
    float o2 = x1 * sv + x2 * cv;
    if (which == 0) { o1 *= 0.125f; o2 *= 0.125f; }   // fold 1/sqrt(64) into q
    p[0] = o1; p[1] = o2;
}

// ---------------- causal flash attention: 64-query tile per block ----------------
__global__ __launch_bounds__(256) void attn_kernel() {
    extern __shared__ float sm[];
    float* Qst = sm;                    // [d=64][qrow 68]
    float* Kst = sm + 64*AT_PAD;        // [d=64][krow 68]
    float* Vsm = sm + 2*64*AT_PAD;      // [krow 64][d 68]
    float* Psm = sm + 3*64*AT_PAD;      // [kcol 64][qrow 68]

    const int tid = threadIdx.x;
    const int tk  = tid & 15;           // 16 col groups
    const int tq  = tid >> 4;           // 16 row groups
    const int qt  = (int)gridDim.y - 1 - (int)blockIdx.y;  // heavy tiles first
    const int bh  = blockIdx.z;
    const int b   = bh >> 4;
    const int h   = bh & 15;

    const size_t base = (size_t)(b * SEQ) * QKVN + h * HD;

    // load Q tile, transposed to [d][qrow]
#pragma unroll
    for (int l = 0; l < 4; l++) {
        int i4  = tid + l * 256;        // 0..1023
        int row = i4 >> 4;              // 0..63
        int d4  = (i4 & 15) << 2;       // 0..60
        float4 v = *(const float4*)&g_qkv[base + (size_t)(qt*64 + row) * QKVN + d4];
        Qst[(d4+0)*AT_PAD + row] = v.x;
        Qst[(d4+1)*AT_PAD + row] = v.y;
        Qst[(d4+2)*AT_PAD + row] = v.z;
        Qst[(d4+3)*AT_PAD + row] = v.w;
    }

    float o_acc[4][4];
    float m_r[4], l_r[4];
#pragma unroll
    for (int i = 0; i < 4; i++) {
        m_r[i] = -1e30f; l_r[i] = 0.f;
#pragma unroll
        for (int j = 0; j < 4; j++) o_acc[i][j] = 0.f;
    }

    for (int kt = 0; kt <= qt; kt++) {
        // load K (transposed) and V tiles
#pragma unroll
        for (int l = 0; l < 4; l++) {
            int i4  = tid + l * 256;
            int row = i4 >> 4;
            int d4  = (i4 & 15) << 2;
            size_t g = base + (size_t)(kt*64 + row) * QKVN + d4;
            float4 kv = *(const float4*)&g_qkv[g + EMB];
            Kst[(d4+0)*AT_PAD + row] = kv.x;
            Kst[(d4+1)*AT_PAD + row] = kv.y;
            Kst[(d4+2)*AT_PAD + row] = kv.z;
            Kst[(d4+3)*AT_PAD + row] = kv.w;
            float4 vv = *(const float4*)&g_qkv[g + 2*EMB];
            *(float4*)&Vsm[row*AT_PAD + d4] = vv;
        }
        __syncthreads();

        // S = Q K^T  (scale already folded into q)
        float s_acc[4][4];
#pragma unroll
        for (int i = 0; i < 4; i++)
#pragma unroll
            for (int j = 0; j < 4; j++) s_acc[i][j] = 0.f;

#pragma unroll 8
        for (int d = 0; d < 64; d++) {
            float4 qv = *(const float4*)&Qst[d*AT_PAD + tq*4];
            float4 kv = *(const float4*)&Kst[d*AT_PAD + tk*4];
            float ra[4] = {qv.x, qv.y, qv.z, qv.w};
            float rb[4] = {kv.x, kv.y, kv.z, kv.w};
#pragma unroll
            for (int i = 0; i < 4; i++)
#pragma unroll
                for (int j = 0; j < 4; j++)
                    s_acc[i][j] = fmaf(ra[i], rb[j], s_acc[i][j]);
        }

        if (kt == qt) {   // diagonal tile: causal mask
#pragma unroll
            for (int i = 0; i < 4; i++) {
                int grow = tq*4 + i;
#pragma unroll
                for (int j = 0; j < 4; j++)
                    if (tk*4 + j > grow) s_acc[i][j] = -1e30f;
            }
        }

        // online softmax; P stored transposed [kcol][qrow]
#pragma unroll
        for (int i = 0; i < 4; i++) {
            float tmax = s_acc[i][0];
#pragma unroll
            for (int j = 1; j < 4; j++) tmax = fmaxf(tmax, s_acc[i][j]);
#pragma unroll
            for (int off = 1; off < 16; off <<= 1)
                tmax = fmaxf(tmax, __shfl_xor_sync(0xffffffffu, tmax, off));
            float mn    = fmaxf(m_r[i], tmax);
            float alpha = __expf(fmaxf(m_r[i] - mn, -80.f));
#pragma unroll
            for (int j = 0; j < 4; j++) o_acc[i][j] *= alpha;
            float rs = 0.f;
#pragma unroll
            for (int j = 0; j < 4; j++) {
                float p = __expf(fmaxf(s_acc[i][j] - mn, -80.f));
                Psm[(tk*4 + j)*AT_PAD + tq*4 + i] = p;
                rs += p;
            }
#pragma unroll
            for (int off = 1; off < 16; off <<= 1)
                rs += __shfl_xor_sync(0xffffffffu, rs, off);
            l_r[i] = l_r[i]*alpha + rs;
            m_r[i] = mn;
        }
        __syncthreads();

        // O += P V
#pragma unroll 8
        for (int kj = 0; kj < 64; kj++) {
            float4 pv = *(const float4*)&Psm[kj*AT_PAD + tq*4];
            float4 vv = *(const float4*)&Vsm[kj*AT_PAD + tk*4];
            float ra[4] = {pv.x,pv.y,pv.z,pv.w};
            float rb[4] = {vv.x,vv.y,vv.z,vv.w};
#pragma unroll
            for (int i = 0; i < 4; i++)
#pragma unroll
                for (int j = 0; j < 4; j++)
                    o_acc[i][j] = fmaf(ra[i], rb[j], o_acc[i][j]);
        }
        __syncthreads();
    }

    // normalize + write [b][s][h][d]
#pragma unroll
    for (int i = 0; i < 4; i++) {
        float inv  = 1.f / l_r[i];
        int   srow = qt*64 + tq*4 + i;
        float4 v = make_float4(o_acc[i][0]*inv, o_acc[i][1]*inv,
                               o_acc[i][2]*inv, o_acc[i][3]*inv);
        *(float4*)&g_attn[(size_t)((b*SEQ + srow)*NH + h) * HD + tk*4] = v;
    }
}

// ---------------- launch ----------------
extern "C" void kernel_launch(void* const* d_in, const int* in_sizes, int n_in,
                              void* d_out, int out_size) {
    const float* x    = (const float*)d_in[0];
    const float* Wqkv = (const float*)d_in[1];
    const float* Wout = (const float*)d_in[2];
    float* out = (float*)d_out;

    cudaFuncSetAttribute(attn_kernel, cudaFuncAttributeMaxDynamicSharedMemorySize, ATT_SMEM);

    qkv_gemm_kernel<<<dim3(QKVN/128, ROWS/128), 256>>>(x, Wqkv);
    rope_kernel<<<(ROWS*2*NH*32)/256, 256>>>();
    attn_kernel<<<dim3(1, SEQ/64, BATCH*NH), 256, ATT_SMEM>>>();
    out_gemm_kernel<<<dim3(EMB/128, ROWS/128), 256>>>(Wout, out);
}

// round 5
// speedup vs baseline: 1.3609x; 1.3609x over previous
#include <cuda_runtime.h>
#include <cuda_bf16.h>
#include <math.h>
#include <stdint.h>

#define SEQ   2048
#define BATCH 2
#define EMB   1024
#define NH    16
#define HD    64
#define QKVN  (3*EMB)       // 3072
#define ROWS  (BATCH*SEQ)   // 4096
#define AT_PAD 68
#define ATT_SMEM (4*64*AT_PAD*4)   // 69632 bytes

// ---------------- device scratch ----------------
__device__ float g_qkv[ROWS * QKVN];        // [row][3*1024] : q|k|v each [h][d]
__device__ float g_attn[ROWS * EMB];        // [b][s][h][d]
__device__ __nv_bfloat16 g_xh[ROWS*EMB],  g_xl[ROWS*EMB];      // x split
__device__ __nv_bfloat16 g_ah[ROWS*EMB],  g_al[ROWS*EMB];      // attn-out split
__device__ __nv_bfloat16 g_Wqh[EMB*QKVN], g_Wql[EMB*QKVN];     // Wqkv^T split [N,K]
__device__ __nv_bfloat16 g_Woh[EMB*EMB],  g_Wol[EMB*EMB];      // Wout^T split [N,K]

// ---------------- helpers ----------------
__device__ __forceinline__ uint32_t smem_u32(const void* p) {
    uint32_t a;
    asm("{ .reg .u64 t; cvta.to.shared.u64 t, %1; cvt.u32.u64 %0, t; }" : "=r"(a) : "l"(p));
    return a;
}
__device__ __forceinline__ void ldsm_x4(uint32_t* r, uint32_t addr) {
    asm volatile("ldmatrix.sync.aligned.m8n8.x4.shared.b16 {%0,%1,%2,%3}, [%4];"
                 : "=r"(r[0]), "=r"(r[1]), "=r"(r[2]), "=r"(r[3]) : "r"(addr));
}
__device__ __forceinline__ void mma_bf16(float* d, const uint32_t* a, const uint32_t* b) {
    asm volatile("mma.sync.aligned.m16n8k16.row.col.f32.bf16.bf16.f32 "
        "{%0,%1,%2,%3}, {%4,%5,%6,%7}, {%8,%9}, {%0,%1,%2,%3};"
        : "+f"(d[0]), "+f"(d[1]), "+f"(d[2]), "+f"(d[3])
        : "r"(a[0]), "r"(a[1]), "r"(a[2]), "r"(a[3]), "r"(b[0]), "r"(b[1]));
}

// ---------------- split conversion kernels ----------------
__device__ __forceinline__ void split1(float x, __nv_bfloat16& h, __nv_bfloat16& l) {
    h = __float2bfloat16(x);
    l = __float2bfloat16(x - __bfloat162float(h));
}

__global__ __launch_bounds__(256) void split4_kernel(const float* __restrict__ in,
                                                     __nv_bfloat16* __restrict__ hi,
                                                     __nv_bfloat16* __restrict__ lo) {
    int i = blockIdx.x * 256 + threadIdx.x;
    float4 v = ((const float4*)in)[i];
    __nv_bfloat16 h0,h1,h2,h3,l0,l1,l2,l3;
    split1(v.x,h0,l0); split1(v.y,h1,l1); split1(v.z,h2,l2); split1(v.w,h3,l3);
    __nv_bfloat162 ph0; ph0.x=h0; ph0.y=h1;
    __nv_bfloat162 ph1; ph1.x=h2; ph1.y=h3;
    __nv_bfloat162 pl0; pl0.x=l0; pl0.y=l1;
    __nv_bfloat162 pl1; pl1.x=l2; pl1.y=l3;
    ((__nv_bfloat162*)hi)[2*i]   = ph0; ((__nv_bfloat162*)hi)[2*i+1] = ph1;
    ((__nv_bfloat162*)lo)[2*i]   = pl0; ((__nv_bfloat162*)lo)[2*i+1] = pl1;
}

// in [K][N] fp32 -> out [N][K] bf16 hi/lo (tiled transpose)
__global__ __launch_bounds__(256) void splitT_kernel(const float* __restrict__ in,
                                                     __nv_bfloat16* __restrict__ hiT,
                                                     __nv_bfloat16* __restrict__ loT,
                                                     int K, int N) {
    __shared__ float t[32][33];
    int n0 = blockIdx.x * 32, k0 = blockIdx.y * 32;
    int tx = threadIdx.x, ty = threadIdx.y;   // block (32,8)
#pragma unroll
    for (int j = 0; j < 4; j++)
        t[ty + j*8][tx] = in[(size_t)(k0 + ty + j*8) * N + n0 + tx];
    __syncthreads();
#pragma unroll
    for (int j = 0; j < 4; j++) {
        int nl = ty + j*8;
        __nv_bfloat16 h, l;
        split1(t[tx][nl], h, l);
        hiT[(size_t)(n0 + nl) * K + k0 + tx] = h;
        loT[(size_t)(n0 + nl) * K + k0 + tx] = l;
    }
}

// ---------------- mma.sync bf16-split GEMM ----------------
// 128x128 CTA tile, BK=32, 8 warps (4x2), cp.async double-buffered.
// smem per matrix per stage: 128 rows x 40 bf16 (pad) = 10240 B; 4 matrices x 2 stages = 80 KB.
#define LDSB   80                     // row stride in bytes (40 bf16)
#define TILE_B (128*LDSB)             // 10240
#define MM_SMEM (8*TILE_B)            // 81920

__device__ __forceinline__ void cpa_tile(uint32_t dst, const __nv_bfloat16* __restrict__ g,
                                         int ld, int row0, int k0, int tid) {
#pragma unroll
    for (int l = 0; l < 2; l++) {
        int idx = tid + l * 256;          // 0..511
        int r   = idx >> 2;               // 0..127
        int seg = idx & 3;                // 16B segment
        const void* src = g + (size_t)(row0 + r) * ld + k0 + seg * 8;
        uint32_t d = dst + r * LDSB + seg * 16;
        asm volatile("cp.async.cg.shared.global [%0], [%1], 16;" :: "r"(d), "l"(src));
    }
}

__device__ __forceinline__ void gemm_mma_body(const __nv_bfloat16* __restrict__ Ah,
                                              const __nv_bfloat16* __restrict__ Al,
                                              const __nv_bfloat16* __restrict__ Bh,
                                              const __nv_bfloat16* __restrict__ Bl,
                                              float* __restrict__ C, int N, int K) {
    extern __shared__ __align__(128) char smem[];
    const uint32_t sb = smem_u32(smem);
    const int tid  = threadIdx.x;
    const int wid  = tid >> 5;
    const int lane = tid & 31;
    const int wm   = wid >> 1;            // 0..3 -> 32-row slice
    const int wn   = wid & 1;             // 0..1 -> 64-col slice
    const int m0   = blockIdx.y * 128;
    const int n0   = blockIdx.x * 128;

    float acc[2][8][4];
#pragma unroll
    for (int m = 0; m < 2; m++)
#pragma unroll
        for (int nf = 0; nf < 8; nf++)
#pragma unroll
            for (int c = 0; c < 4; c++) acc[m][nf][c] = 0.f;

    // ldmatrix lane offsets (bytes, relative to fragment base)
    const uint32_t aoff = (lane & 15) * LDSB + (lane >> 4) * 16;
    const uint32_t boff = ((lane & 7) + ((lane >> 4) << 3)) * LDSB + (((lane >> 3) & 1) * 16);

    const int NIT = K / 32;

    // prefetch iteration 0 into stage 0
    cpa_tile(sb + 0*TILE_B, Ah, K, m0, 0, tid);
    cpa_tile(sb + 1*TILE_B, Al, K, m0, 0, tid);
    cpa_tile(sb + 2*TILE_B, Bh, K, n0, 0, tid);
    cpa_tile(sb + 3*TILE_B, Bl, K, n0, 0, tid);
    asm volatile("cp.async.commit_group;" ::: "memory");

    for (int it = 0; it < NIT; it++) {
        const int s = it & 1;
        if (it + 1 < NIT) {
            const uint32_t nb = sb + (s ^ 1) * 4 * TILE_B;
            const int k2 = (it + 1) * 32;
            cpa_tile(nb + 0*TILE_B, Ah, K, m0, k2, tid);
            cpa_tile(nb + 1*TILE_B, Al, K, m0, k2, tid);
            cpa_tile(nb + 2*TILE_B, Bh, K, n0, k2, tid);
            cpa_tile(nb + 3*TILE_B, Bl, K, n0, k2, tid);
            asm volatile("cp.async.commit_group;" ::: "memory");
            asm volatile("cp.async.wait_group 1;" ::: "memory");
        } else {
            asm volatile("cp.async.wait_group 0;" ::: "memory");
        }
        __syncthreads();

        const uint32_t cb    = sb + s * 4 * TILE_B;
        const uint32_t baseAh = cb + 0*TILE_B + wm * 32 * LDSB;
        const uint32_t baseAl = cb + 1*TILE_B + wm * 32 * LDSB;
        const uint32_t baseBh = cb + 2*TILE_B + wn * 64 * LDSB;
        const uint32_t baseBl = cb + 3*TILE_B + wn * 64 * LDSB;

#pragma unroll
        for (int ks = 0; ks < 2; ks++) {
            const uint32_t kb = ks * 32;     // 16 bf16 = 32 bytes
            uint32_t ah[2][4], al[2][4];
            ldsm_x4(ah[0], baseAh + aoff + kb);
            ldsm_x4(ah[1], baseAh + 16*LDSB + aoff + kb);
            ldsm_x4(al[0], baseAl + aoff + kb);
            ldsm_x4(al[1], baseAl + 16*LDSB + aoff + kb);
#pragma unroll
            for (int nc = 0; nc < 4; nc++) {
                uint32_t bh[4], bl[4];
                ldsm_x4(bh, baseBh + nc * 16 * LDSB + boff + kb);
                ldsm_x4(bl, baseBl + nc * 16 * LDSB + boff + kb);
#pragma unroll
                for (int m = 0; m < 2; m++) {
                    mma_bf16(acc[m][nc*2],   ah[m], bh);
                    mma_bf16(acc[m][nc*2+1], ah[m], bh + 2);
                    mma_bf16(acc[m][nc*2],   ah[m], bl);
                    mma_bf16(acc[m][nc*2+1], ah[m], bl + 2);
                    mma_bf16(acc[m][nc*2],   al[m], bh);
                    mma_bf16(acc[m][nc*2+1], al[m], bh + 2);
                }
            }
        }
        __syncthreads();
    }

    // epilogue: fragment layout -> global fp32
    const int r0 = m0 + wm * 32 + (lane >> 2);
    const int c0 = n0 + wn * 64 + (lane & 3) * 2;
#pragma unroll
    for (int m = 0; m < 2; m++)
#pragma unroll
        for (int nf = 0; nf < 8; nf++) {
            const float* a = acc[m][nf];
            const int r = r0 + m * 16;
            const int c = c0 + nf * 8;
            *(float2*)&C[(size_t)r * N + c]       = make_float2(a[0], a[1]);
            *(float2*)&C[(size_t)(r + 8) * N + c] = make_float2(a[2], a[3]);
        }
}

__global__ __launch_bounds__(256) void qkv_mma_kernel() {
    gemm_mma_body(g_xh, g_xl, g_Wqh, g_Wql, g_qkv, QKVN, EMB);
}
__global__ __launch_bounds__(256) void out_mma_kernel(float* __restrict__ out) {
    gemm_mma_body(g_ah, g_al, g_Woh, g_Wol, out, EMB, EMB);
}

// ---------------- RoPE (in place on q and k halves of g_qkv; q pre-scaled) ----------------
__global__ void rope_kernel() {
    int idx = blockIdx.x * blockDim.x + threadIdx.x;
    int i     = idx & 31;
    int h     = (idx >> 5) & 15;
    int which = (idx >> 9) & 1;          // 0 = q, 1 = k
    int row   = idx >> 10;               // 0..4095
    if (row >= ROWS) return;
    int s = row & (SEQ - 1);
    float freq = powf(10000.f, -(float)(2*i) / 64.f);
    float ang  = (float)s * freq;
    float sv, cv;
    sincosf(ang, &sv, &cv);
    float* p = &g_qkv[(size_t)row * QKVN + which * EMB + h * HD + 2*i];
    float x1 = p[0], x2 = p[1];
    float o1 = x1 * cv - x2 * sv;
    float o2 = x1 * sv + x2 * cv;
    if (which == 0) { o1 *= 0.125f; o2 *= 0.125f; }   // fold 1/sqrt(64) into q
    p[0] = o1; p[1] = o2;
}

// ---------------- causal flash attention: 64-query tile per block ----------------
__global__ __launch_bounds__(256) void attn_kernel() {
    extern __shared__ float sm[];
    float* Qst = sm;                    // [d=64][qrow 68]
    float* Kst = sm + 64*AT_PAD;        // [d=64][krow 68]
    float* Vsm = sm + 2*64*AT_PAD;      // [krow 64][d 68]
    float* Psm = sm + 3*64*AT_PAD;      // [kcol 64][qrow 68]

    const int tid = threadIdx.x;
    const int tk  = tid & 15;
    const int tq  = tid >> 4;
    const int qt  = (int)gridDim.y - 1 - (int)blockIdx.y;
    const int bh  = blockIdx.z;
    const int b   = bh >> 4;
    const int h   = bh & 15;

    const size_t base = (size_t)(b * SEQ) * QKVN + h * HD;

#pragma unroll
    for (int l = 0; l < 4; l++) {
        int i4  = tid + l * 256;
        int row = i4 >> 4;
        int d4  = (i4 & 15) << 2;
        float4 v = *(const float4*)&g_qkv[base + (size_t)(qt*64 + row) * QKVN + d4];
        Qst[(d4+0)*AT_PAD + row] = v.x;
        Qst[(d4+1)*AT_PAD + row] = v.y;
        Qst[(d4+2)*AT_PAD + row] = v.z;
        Qst[(d4+3)*AT_PAD + row] = v.w;
    }

    float o_acc[4][4];
    float m_r[4], l_r[4];
#pragma unroll
    for (int i = 0; i < 4; i++) {
        m_r[i] = -1e30f; l_r[i] = 0.f;
#pragma unroll
        for (int j = 0; j < 4; j++) o_acc[i][j] = 0.f;
    }

    for (int kt = 0; kt <= qt; kt++) {
#pragma unroll
        for (int l = 0; l < 4; l++) {
            int i4  = tid + l * 256;
            int row = i4 >> 4;
            int d4  = (i4 & 15) << 2;
            size_t g = base + (size_t)(kt*64 + row) * QKVN + d4;
            float4 kv = *(const float4*)&g_qkv[g + EMB];
            Kst[(d4+0)*AT_PAD + row] = kv.x;
            Kst[(d4+1)*AT_PAD + row] = kv.y;
            Kst[(d4+2)*AT_PAD + row] = kv.z;
            Kst[(d4+3)*AT_PAD + row] = kv.w;
            float4 vv = *(const float4*)&g_qkv[g + 2*EMB];
            *(float4*)&Vsm[row*AT_PAD + d4] = vv;
        }
        __syncthreads();

        float s_acc[4][4];
#pragma unroll
        for (int i = 0; i < 4; i++)
#pragma unroll
            for (int j = 0; j < 4; j++) s_acc[i][j] = 0.f;

#pragma unroll 8
        for (int d = 0; d < 64; d++) {
            float4 qv = *(const float4*)&Qst[d*AT_PAD + tq*4];
            float4 kv = *(const float4*)&Kst[d*AT_PAD + tk*4];
            float ra[4] = {qv.x, qv.y, qv.z, qv.w};
            float rb[4] = {kv.x, kv.y, kv.z, kv.w};
#pragma unroll
            for (int i = 0; i < 4; i++)
#pragma unroll
                for (int j = 0; j < 4; j++)
                    s_acc[i][j] = fmaf(ra[i], rb[j], s_acc[i][j]);
        }

        if (kt == qt) {
#pragma unroll
            for (int i = 0; i < 4; i++) {
                int grow = tq*4 + i;
#pragma unroll
                for (int j = 0; j < 4; j++)
                    if (tk*4 + j > grow) s_acc[i][j] = -1e30f;
            }
        }

#pragma unroll
        for (int i = 0; i < 4; i++) {
            float tmax = s_acc[i][0];
#pragma unroll
            for (int j = 1; j < 4; j++) tmax = fmaxf(tmax, s_acc[i][j]);
#pragma unroll
            for (int off = 1; off < 16; off <<= 1)
                tmax = fmaxf(tmax, __shfl_xor_sync(0xffffffffu, tmax, off));
            float mn    = fmaxf(m_r[i], tmax);
            float alpha = __expf(fmaxf(m_r[i] - mn, -80.f));
#pragma unroll
            for (int j = 0; j < 4; j++) o_acc[i][j] *= alpha;
            float rs = 0.f;
#pragma unroll
            for (int j = 0; j < 4; j++) {
                float p = __expf(fmaxf(s_acc[i][j] - mn, -80.f));
                Psm[(tk*4 + j)*AT_PAD + tq*4 + i] = p;
                rs += p;
            }
#pragma unroll
            for (int off = 1; off < 16; off <<= 1)
                rs += __shfl_xor_sync(0xffffffffu, rs, off);
            l_r[i] = l_r[i]*alpha + rs;
            m_r[i] = mn;
        }
        __syncthreads();

#pragma unroll 8
        for (int kj = 0; kj < 64; kj++) {
            float4 pv = *(const float4*)&Psm[kj*AT_PAD + tq*4];
            float4 vv = *(const float4*)&Vsm[kj*AT_PAD + tk*4];
            float ra[4] = {pv.x,pv.y,pv.z,pv.w};
            float rb[4] = {vv.x,vv.y,vv.z,vv.w};
#pragma unroll
            for (int i = 0; i < 4; i++)
#pragma unroll
                for (int j = 0; j < 4; j++)
                    o_acc[i][j] = fmaf(ra[i], rb[j], o_acc[i][j]);
        }
        __syncthreads();
    }

#pragma unroll
    for (int i = 0; i < 4; i++) {
        float inv  = 1.f / l_r[i];
        int   srow = qt*64 + tq*4 + i;
        float4 v = make_float4(o_acc[i][0]*inv, o_acc[i][1]*inv,
                               o_acc[i][2]*inv, o_acc[i][3]*inv);
        *(float4*)&g_attn[(size_t)((b*SEQ + srow)*NH + h) * HD + tk*4] = v;
    }
}

// ---------------- launch ----------------
extern "C" void kernel_launch(void* const* d_in, const int* in_sizes, int n_in,
                              void* d_out, int out_size) {
    const float* x    = (const float*)d_in[0];
    const float* Wqkv = (const float*)d_in[1];
    const float* Wout = (const float*)d_in[2];
    float* out = (float*)d_out;

    cudaFuncSetAttribute(attn_kernel,    cudaFuncAttributeMaxDynamicSharedMemorySize, ATT_SMEM);
    cudaFuncSetAttribute(qkv_mma_kernel, cudaFuncAttributeMaxDynamicSharedMemorySize, MM_SMEM);
    cudaFuncSetAttribute(out_mma_kernel, cudaFuncAttributeMaxDynamicSharedMemorySize, MM_SMEM);

    __nv_bfloat16 *p_xh, *p_xl, *p_Wqh, *p_Wql, *p_Woh, *p_Wol, *p_ah, *p_al;
    float *p_attn;
    cudaGetSymbolAddress((void**)&p_xh,  g_xh);
    cudaGetSymbolAddress((void**)&p_xl,  g_xl);
    cudaGetSymbolAddress((void**)&p_Wqh, g_Wqh);
    cudaGetSymbolAddress((void**)&p_Wql, g_Wql);
    cudaGetSymbolAddress((void**)&p_Woh, g_Woh);
    cudaGetSymbolAddress((void**)&p_Wol, g_Wol);
    cudaGetSymbolAddress((void**)&p_ah,  g_ah);
    cudaGetSymbolAddress((void**)&p_al,  g_al);
    cudaGetSymbolAddress((void**)&p_attn, g_attn);

    // x, Wqkv splits
    split4_kernel<<<(ROWS*EMB)/4/256, 256>>>(x, p_xh, p_xl);
    splitT_kernel<<<dim3(QKVN/32, EMB/32), dim3(32,8)>>>(Wqkv, p_Wqh, p_Wql, EMB, QKVN);
    // QKV projection (HMMA tensor path)
    qkv_mma_kernel<<<dim3(QKVN/128, ROWS/128), 256, MM_SMEM>>>();
    // RoPE + attention (fp32)
    rope_kernel<<<(ROWS*2*NH*32)/256, 256>>>();
    attn_kernel<<<dim3(1, SEQ/64, BATCH*NH), 256, ATT_SMEM>>>();
    // output projection (HMMA tensor path)
    split4_kernel<<<(ROWS*EMB)/4/256, 256>>>(p_attn, p_ah, p_al);
    splitT_kernel<<<dim3(EMB/32, EMB/32), dim3(32,8)>>>(Wout, p_Woh, p_Wol, EMB, EMB);
    out_mma_kernel<<<dim3(EMB/128, ROWS/128), 256, MM_SMEM>>>(out);
}

// round 6
// speedup vs baseline: 2.2185x; 1.6301x over previous
#include <cuda_runtime.h>
#include <cuda_bf16.h>
#include <math.h>
#include <stdint.h>

#define SEQ   2048
#define BATCH 2
#define EMB   1024
#define NH    16
#define HD    64
#define QKVN  (3*EMB)       // 3072
#define ROWS  (BATCH*SEQ)   // 4096

// ---------------- device scratch ----------------
__device__ float g_qkv[ROWS * QKVN];        // [row][3*1024] : q|k|v each [h][d]
__device__ __nv_bfloat16 g_xh[ROWS*EMB],  g_xl[ROWS*EMB];      // x split
__device__ __nv_bfloat16 g_ah[ROWS*EMB],  g_al[ROWS*EMB];      // attn-out split (written by attention)
__device__ __nv_bfloat16 g_Wqh[EMB*QKVN], g_Wql[EMB*QKVN];     // Wqkv^T split [N,K]
__device__ __nv_bfloat16 g_Woh[EMB*EMB],  g_Wol[EMB*EMB];      // Wout^T split [N,K]

// ---------------- helpers ----------------
__device__ __forceinline__ uint32_t smem_u32(const void* p) {
    uint32_t a;
    asm("{ .reg .u64 t; cvta.to.shared.u64 t, %1; cvt.u32.u64 %0, t; }" : "=r"(a) : "l"(p));
    return a;
}
__device__ __forceinline__ void ldsm_x4(uint32_t* r, uint32_t addr) {
    asm volatile("ldmatrix.sync.aligned.m8n8.x4.shared.b16 {%0,%1,%2,%3}, [%4];"
                 : "=r"(r[0]), "=r"(r[1]), "=r"(r[2]), "=r"(r[3]) : "r"(addr));
}
__device__ __forceinline__ void mma_bf16(float* d, const uint32_t* a, const uint32_t* b) {
    asm volatile("mma.sync.aligned.m16n8k16.row.col.f32.bf16.bf16.f32 "
        "{%0,%1,%2,%3}, {%4,%5,%6,%7}, {%8,%9}, {%0,%1,%2,%3};"
        : "+f"(d[0]), "+f"(d[1]), "+f"(d[2]), "+f"(d[3])
        : "r"(a[0]), "r"(a[1]), "r"(a[2]), "r"(a[3]), "r"(b[0]), "r"(b[1]));
}
__device__ __forceinline__ uint32_t pack_bf(float a, float b) {
    __nv_bfloat162 t; t.x = __float2bfloat16(a); t.y = __float2bfloat16(b);
    return *(uint32_t*)&t;
}
__device__ __forceinline__ float bf_hi(float x) {
    return __bfloat162float(__float2bfloat16(x));
}

// ---------------- split conversion kernels ----------------
__device__ __forceinline__ void split1(float x, __nv_bfloat16& h, __nv_bfloat16& l) {
    h = __float2bfloat16(x);
    l = __float2bfloat16(x - __bfloat162float(h));
}

__global__ __launch_bounds__(256) void split4_kernel(const float* __restrict__ in,
                                                     __nv_bfloat16* __restrict__ hi,
                                                     __nv_bfloat16* __restrict__ lo) {
    int i = blockIdx.x * 256 + threadIdx.x;
    float4 v = ((const float4*)in)[i];
    __nv_bfloat16 h0,h1,h2,h3,l0,l1,l2,l3;
    split1(v.x,h0,l0); split1(v.y,h1,l1); split1(v.z,h2,l2); split1(v.w,h3,l3);
    __nv_bfloat162 ph0; ph0.x=h0; ph0.y=h1;
    __nv_bfloat162 ph1; ph1.x=h2; ph1.y=h3;
    __nv_bfloat162 pl0; pl0.x=l0; pl0.y=l1;
    __nv_bfloat162 pl1; pl1.x=l2; pl1.y=l3;
    ((__nv_bfloat162*)hi)[2*i]   = ph0; ((__nv_bfloat162*)hi)[2*i+1] = ph1;
    ((__nv_bfloat162*)lo)[2*i]   = pl0; ((__nv_bfloat162*)lo)[2*i+1] = pl1;
}

// in [K][N] fp32 -> out [N][K] bf16 hi/lo (tiled transpose)
__global__ __launch_bounds__(256) void splitT_kernel(const float* __restrict__ in,
                                                     __nv_bfloat16* __restrict__ hiT,
                                                     __nv_bfloat16* __restrict__ loT,
                                                     int K, int N) {
    __shared__ float t[32][33];
    int n0 = blockIdx.x * 32, k0 = blockIdx.y * 32;
    int tx = threadIdx.x, ty = threadIdx.y;   // block (32,8)
#pragma unroll
    for (int j = 0; j < 4; j++)
        t[ty + j*8][tx] = in[(size_t)(k0 + ty + j*8) * N + n0 + tx];
    __syncthreads();
#pragma unroll
    for (int j = 0; j < 4; j++) {
        int nl = ty + j*8;
        __nv_bfloat16 h, l;
        split1(t[tx][nl], h, l);
        hiT[(size_t)(n0 + nl) * K + k0 + tx] = h;
        loT[(size_t)(n0 + nl) * K + k0 + tx] = l;
    }
}

// ---------------- mma.sync bf16-split GEMM (unchanged from round 5) ----------------
#define LDSB   80
#define TILE_B (128*LDSB)
#define MM_SMEM (8*TILE_B)

__device__ __forceinline__ void cpa_tile(uint32_t dst, const __nv_bfloat16* __restrict__ g,
                                         int ld, int row0, int k0, int tid) {
#pragma unroll
    for (int l = 0; l < 2; l++) {
        int idx = tid + l * 256;
        int r   = idx >> 2;
        int seg = idx & 3;
        const void* src = g + (size_t)(row0 + r) * ld + k0 + seg * 8;
        uint32_t d = dst + r * LDSB + seg * 16;
        asm volatile("cp.async.cg.shared.global [%0], [%1], 16;" :: "r"(d), "l"(src));
    }
}

__device__ __forceinline__ void gemm_mma_body(const __nv_bfloat16* __restrict__ Ah,
                                              const __nv_bfloat16* __restrict__ Al,
                                              const __nv_bfloat16* __restrict__ Bh,
                                              const __nv_bfloat16* __restrict__ Bl,
                                              float* __restrict__ C, int N, int K) {
    extern __shared__ __align__(128) char smem[];
    const uint32_t sb = smem_u32(smem);
    const int tid  = threadIdx.x;
    const int wid  = tid >> 5;
    const int lane = tid & 31;
    const int wm   = wid >> 1;
    const int wn   = wid & 1;
    const int m0   = blockIdx.y * 128;
    const int n0   = blockIdx.x * 128;

    float acc[2][8][4];
#pragma unroll
    for (int m = 0; m < 2; m++)
#pragma unroll
        for (int nf = 0; nf < 8; nf++)
#pragma unroll
            for (int c = 0; c < 4; c++) acc[m][nf][c] = 0.f;

    const uint32_t aoff = (lane & 15) * LDSB + (lane >> 4) * 16;
    const uint32_t boff = ((lane & 7) + ((lane >> 4) << 3)) * LDSB + (((lane >> 3) & 1) * 16);

    const int NIT = K / 32;

    cpa_tile(sb + 0*TILE_B, Ah, K, m0, 0, tid);
    cpa_tile(sb + 1*TILE_B, Al, K, m0, 0, tid);
    cpa_tile(sb + 2*TILE_B, Bh, K, n0, 0, tid);
    cpa_tile(sb + 3*TILE_B, Bl, K, n0, 0, tid);
    asm volatile("cp.async.commit_group;" ::: "memory");

    for (int it = 0; it < NIT; it++) {
        const int s = it & 1;
        if (it + 1 < NIT) {
            const uint32_t nb = sb + (s ^ 1) * 4 * TILE_B;
            const int k2 = (it + 1) * 32;
            cpa_tile(nb + 0*TILE_B, Ah, K, m0, k2, tid);
            cpa_tile(nb + 1*TILE_B, Al, K, m0, k2, tid);
            cpa_tile(nb + 2*TILE_B, Bh, K, n0, k2, tid);
            cpa_tile(nb + 3*TILE_B, Bl, K, n0, k2, tid);
            asm volatile("cp.async.commit_group;" ::: "memory");
            asm volatile("cp.async.wait_group 1;" ::: "memory");
        } else {
            asm volatile("cp.async.wait_group 0;" ::: "memory");
        }
        __syncthreads();

        const uint32_t cb     = sb + s * 4 * TILE_B;
        const uint32_t baseAh = cb + 0*TILE_B + wm * 32 * LDSB;
        const uint32_t baseAl = cb + 1*TILE_B + wm * 32 * LDSB;
        const uint32_t baseBh = cb + 2*TILE_B + wn * 64 * LDSB;
        const uint32_t baseBl = cb + 3*TILE_B + wn * 64 * LDSB;

#pragma unroll
        for (int ks = 0; ks < 2; ks++) {
            const uint32_t kb = ks * 32;
            uint32_t ah[2][4], al[2][4];
            ldsm_x4(ah[0], baseAh + aoff + kb);
            ldsm_x4(ah[1], baseAh + 16*LDSB + aoff + kb);
            ldsm_x4(al[0], baseAl + aoff + kb);
            ldsm_x4(al[1], baseAl + 16*LDSB + aoff + kb);
#pragma unroll
            for (int nc = 0; nc < 4; nc++) {
                uint32_t bh[4], bl[4];
                ldsm_x4(bh, baseBh + nc * 16 * LDSB + boff + kb);
                ldsm_x4(bl, baseBl + nc * 16 * LDSB + boff + kb);
#pragma unroll
                for (int m = 0; m < 2; m++) {
                    mma_bf16(acc[m][nc*2],   ah[m], bh);
                    mma_bf16(acc[m][nc*2+1], ah[m], bh + 2);
                    mma_bf16(acc[m][nc*2],   ah[m], bl);
                    mma_bf16(acc[m][nc*2+1], ah[m], bl + 2);
                    mma_bf16(acc[m][nc*2],   al[m], bh);
                    mma_bf16(acc[m][nc*2+1], al[m], bh + 2);
                }
            }
        }
        __syncthreads();
    }

    const int r0 = m0 + wm * 32 + (lane >> 2);
    const int c0 = n0 + wn * 64 + (lane & 3) * 2;
#pragma unroll
    for (int m = 0; m < 2; m++)
#pragma unroll
        for (int nf = 0; nf < 8; nf++) {
            const float* a = acc[m][nf];
            const int r = r0 + m * 16;
            const int c = c0 + nf * 8;
            *(float2*)&C[(size_t)r * N + c]       = make_float2(a[0], a[1]);
            *(float2*)&C[(size_t)(r + 8) * N + c] = make_float2(a[2], a[3]);
        }
}

__global__ __launch_bounds__(256) void qkv_mma_kernel() {
    gemm_mma_body(g_xh, g_xl, g_Wqh, g_Wql, g_qkv, QKVN, EMB);
}
__global__ __launch_bounds__(256) void out_mma_kernel(float* __restrict__ out) {
    gemm_mma_body(g_ah, g_al, g_Woh, g_Wol, out, EMB, EMB);
}

// ---------------- RoPE (in place; q pre-scaled by 1/8) ----------------
__global__ void rope_kernel() {
    int idx = blockIdx.x * blockDim.x + threadIdx.x;
    int i     = idx & 31;
    int h     = (idx >> 5) & 15;
    int which = (idx >> 9) & 1;
    int row   = idx >> 10;
    if (row >= ROWS) return;
    int s = row & (SEQ - 1);
    float freq = powf(10000.f, -(float)(2*i) / 64.f);
    float ang  = (float)s * freq;
    float sv, cv;
    sincosf(ang, &sv, &cv);
    float* p = &g_qkv[(size_t)row * QKVN + which * EMB + h * HD + 2*i];
    float x1 = p[0], x2 = p[1];
    float o1 = x1 * cv - x2 * sv;
    float o2 = x1 * sv + x2 * cv;
    if (which == 0) { o1 *= 0.125f; o2 *= 0.125f; }
    p[0] = o1; p[1] = o2;
}

// ---------------- tensor-core flash attention ----------------
// CTA: 128 q-rows x one (b,h). 8 warps x 16 rows. k processed in 64-row tiles.
// smem rows padded to 72 bf16 (144 B) -> conflict-free ldmatrix.
#define AQS   144                       // row stride bytes
#define SQH   0
#define SQL   (128*AQS)                 // 18432
#define SKH   (2*128*AQS)               // 36864
#define SKL   (SKH +  64*AQS)           // 46080
#define SVH   (SKL +  64*AQS)           // 55296
#define SVL   (SVH +  64*AQS)           // 64512
#define ATT_SMEM (SVL + 64*AQS)         // 73728

__global__ __launch_bounds__(256, 2) void attn_mma_kernel() {
    extern __shared__ __align__(128) char sm[];
    const uint32_t sb = smem_u32(sm);
    const int tid  = threadIdx.x;
    const int w    = tid >> 5;
    const int lane = tid & 31;
    const int qt   = 15 - (int)blockIdx.y;      // heavy tiles first
    const int bh   = blockIdx.z;
    const int b    = bh >> 4;
    const int h    = bh & 15;
    const int qbase = qt * 128;
    const size_t rowb = (size_t)b * SEQ;

    // ---- load Q tile (128x64 fp32) -> hi/lo bf16 smem ----
#pragma unroll
    for (int l = 0; l < 8; l++) {
        int idx = tid + l * 256;          // 0..2047
        int r   = idx >> 4;               // 0..127
        int f4  = idx & 15;               // 0..15
        float4 v = *(const float4*)&g_qkv[(rowb + qbase + r) * QKVN + h * HD + f4 * 4];
        uint32_t off = r * AQS + f4 * 8;
        *(uint32_t*)(sm + SQH + off)     = pack_bf(v.x, v.y);
        *(uint32_t*)(sm + SQH + off + 4) = pack_bf(v.z, v.w);
        *(uint32_t*)(sm + SQL + off)     = pack_bf(v.x - bf_hi(v.x), v.y - bf_hi(v.y));
        *(uint32_t*)(sm + SQL + off + 4) = pack_bf(v.z - bf_hi(v.z), v.w - bf_hi(v.w));
    }

    const uint32_t aoff = (lane & 15) * AQS + (lane >> 4) * 16;
    const uint32_t boff = ((lane & 7) + ((lane >> 4) << 3)) * AQS + ((lane >> 3) & 1) * 16;
    const int r0 = qbase + w * 16;

    float o[8][4];
#pragma unroll
    for (int t = 0; t < 8; t++)
#pragma unroll
        for (int c = 0; c < 4; c++) o[t][c] = 0.f;
    float m0r = -1e30f, m1r = -1e30f, l0r = 0.f, l1r = 0.f;

    const int nkt = 2 * qt + 2;
    for (int kt = 0; kt < nkt; kt++) {
        __syncthreads();   // previous iteration's K/V reads complete

        // ---- load K tile (64x64) row-major hi/lo ----
#pragma unroll
        for (int l = 0; l < 4; l++) {
            int idx = tid + l * 256;
            int r   = idx >> 4;
            int f4  = idx & 15;
            float4 v = *(const float4*)&g_qkv[(rowb + kt*64 + r) * QKVN + EMB + h * HD + f4 * 4];
            uint32_t off = r * AQS + f4 * 8;
            *(uint32_t*)(sm + SKH + off)     = pack_bf(v.x, v.y);
            *(uint32_t*)(sm + SKH + off + 4) = pack_bf(v.z, v.w);
            *(uint32_t*)(sm + SKL + off)     = pack_bf(v.x - bf_hi(v.x), v.y - bf_hi(v.y));
            *(uint32_t*)(sm + SKL + off + 4) = pack_bf(v.z - bf_hi(v.z), v.w - bf_hi(v.w));
        }
        // ---- load V tile (64x64) transposed to [d][s] hi/lo ----
#pragma unroll
        for (int l = 0; l < 4; l++) {
            int idx = tid + l * 256;      // 0..1023
            int s   = idx & 63;
            int f4  = idx >> 6;           // 0..15
            float4 v = *(const float4*)&g_qkv[(rowb + kt*64 + s) * QKVN + 2*EMB + h * HD + f4 * 4];
            float vv[4] = {v.x, v.y, v.z, v.w};
#pragma unroll
            for (int j = 0; j < 4; j++) {
                uint32_t off = (f4*4 + j) * AQS + s * 2;
                float hi = bf_hi(vv[j]);
                *(__nv_bfloat16*)(sm + SVH + off) = __float2bfloat16(vv[j]);
                *(__nv_bfloat16*)(sm + SVL + off) = __float2bfloat16(vv[j] - hi);
            }
        }
        __syncthreads();

        if (kt * 64 <= r0 + 15) {    // tile not fully masked for this warp
            // ---- S = Q K^T (3-term split) ----
            float st[8][4];
#pragma unroll
            for (int t = 0; t < 8; t++)
#pragma unroll
                for (int c = 0; c < 4; c++) st[t][c] = 0.f;

#pragma unroll
            for (int j = 0; j < 4; j++) {
                uint32_t qh[4], ql[4];
                ldsm_x4(qh, sb + SQH + w*16*AQS + aoff + j*32);
                ldsm_x4(ql, sb + SQL + w*16*AQS + aoff + j*32);
#pragma unroll
                for (int nb = 0; nb < 4; nb++) {
                    uint32_t kh[4], kl[4];
                    ldsm_x4(kh, sb + SKH + nb*16*AQS + boff + j*32);
                    ldsm_x4(kl, sb + SKL + nb*16*AQS + boff + j*32);
                    mma_bf16(st[2*nb],   qh, kh);
                    mma_bf16(st[2*nb+1], qh, kh + 2);
                    mma_bf16(st[2*nb],   qh, kl);
                    mma_bf16(st[2*nb+1], qh, kl + 2);
                    mma_bf16(st[2*nb],   ql, kh);
                    mma_bf16(st[2*nb+1], ql, kh + 2);
                }
            }

            // ---- causal mask (diagonal-overlapping tiles only) ----
            const int rq0 = r0 + (lane >> 2);
            if (kt * 64 + 63 > r0) {
#pragma unroll
                for (int t = 0; t < 8; t++) {
                    int c = kt*64 + t*8 + (lane & 3)*2;
                    if (c     > rq0)     st[t][0] = -1e30f;
                    if (c + 1 > rq0)     st[t][1] = -1e30f;
                    if (c     > rq0 + 8) st[t][2] = -1e30f;
                    if (c + 1 > rq0 + 8) st[t][3] = -1e30f;
                }
            }

            // ---- online softmax ----
            float rm0 = -1e30f, rm1 = -1e30f;
#pragma unroll
            for (int t = 0; t < 8; t++) {
                rm0 = fmaxf(rm0, fmaxf(st[t][0], st[t][1]));
                rm1 = fmaxf(rm1, fmaxf(st[t][2], st[t][3]));
            }
            rm0 = fmaxf(rm0, __shfl_xor_sync(0xffffffffu, rm0, 1));
            rm0 = fmaxf(rm0, __shfl_xor_sync(0xffffffffu, rm0, 2));
            rm1 = fmaxf(rm1, __shfl_xor_sync(0xffffffffu, rm1, 1));
            rm1 = fmaxf(rm1, __shfl_xor_sync(0xffffffffu, rm1, 2));
            float mn0 = fmaxf(m0r, rm0), mn1 = fmaxf(m1r, rm1);
            float al0 = __expf(m0r - mn0), al1 = __expf(m1r - mn1);
            float rs0 = 0.f, rs1 = 0.f;
#pragma unroll
            for (int t = 0; t < 8; t++) {
                st[t][0] = __expf(st[t][0] - mn0);
                st[t][1] = __expf(st[t][1] - mn0);
                st[t][2] = __expf(st[t][2] - mn1);
                st[t][3] = __expf(st[t][3] - mn1);
                rs0 += st[t][0] + st[t][1];
                rs1 += st[t][2] + st[t][3];
            }
            rs0 += __shfl_xor_sync(0xffffffffu, rs0, 1);
            rs0 += __shfl_xor_sync(0xffffffffu, rs0, 2);
            rs1 += __shfl_xor_sync(0xffffffffu, rs1, 1);
            rs1 += __shfl_xor_sync(0xffffffffu, rs1, 2);
            l0r = l0r * al0 + rs0;
            l1r = l1r * al1 + rs1;
            m0r = mn0; m1r = mn1;
#pragma unroll
            for (int t = 0; t < 8; t++) {
                o[t][0] *= al0; o[t][1] *= al0;
                o[t][2] *= al1; o[t][3] *= al1;
            }

            // ---- O += P V (3-term split) ----
#pragma unroll
            for (int j = 0; j < 4; j++) {
                // pack P fragment (A m16k16) from S tiles 2j, 2j+1
                float p00 = st[2*j][0],   p01 = st[2*j][1];
                float p10 = st[2*j][2],   p11 = st[2*j][3];
                float q00 = st[2*j+1][0], q01 = st[2*j+1][1];
                float q10 = st[2*j+1][2], q11 = st[2*j+1][3];
                uint32_t ph[4], pl[4];
                ph[0] = pack_bf(p00, p01); ph[1] = pack_bf(p10, p11);
                ph[2] = pack_bf(q00, q01); ph[3] = pack_bf(q10, q11);
                pl[0] = pack_bf(p00 - bf_hi(p00), p01 - bf_hi(p01));
                pl[1] = pack_bf(p10 - bf_hi(p10), p11 - bf_hi(p11));
                pl[2] = pack_bf(q00 - bf_hi(q00), q01 - bf_hi(q01));
                pl[3] = pack_bf(q10 - bf_hi(q10), q11 - bf_hi(q11));
#pragma unroll
                for (int db = 0; db < 4; db++) {
                    uint32_t vh[4], vl[4];
                    ldsm_x4(vh, sb + SVH + db*16*AQS + boff + j*32);
                    ldsm_x4(vl, sb + SVL + db*16*AQS + boff + j*32);
                    mma_bf16(o[2*db],   ph, vh);
                    mma_bf16(o[2*db+1], ph, vh + 2);
                    mma_bf16(o[2*db],   ph, vl);
                    mma_bf16(o[2*db+1], ph, vl + 2);
                    mma_bf16(o[2*db],   pl, vh);
                    mma_bf16(o[2*db+1], pl, vh + 2);
                }
            }
        }
    }

    // ---- epilogue: normalize, split to bf16 hi/lo, write g_ah/g_al ----
    const float inv0 = 1.f / l0r, inv1 = 1.f / l1r;
    const int rq0 = qbase + w*16 + (lane >> 2);
#pragma unroll
    for (int t = 0; t < 8; t++) {
        int col = h * HD + t*8 + (lane & 3) * 2;
        float a0 = o[t][0] * inv0, a1 = o[t][1] * inv0;
        float a2 = o[t][2] * inv1, a3 = o[t][3] * inv1;
        size_t i0 = (rowb + rq0)     * EMB + col;
        size_t i1 = (rowb + rq0 + 8) * EMB + col;
        *(uint32_t*)&g_ah[i0] = pack_bf(a0, a1);
        *(uint32_t*)&g_al[i0] = pack_bf(a0 - bf_hi(a0), a1 - bf_hi(a1));
        *(uint32_t*)&g_ah[i1] = pack_bf(a2, a3);
        *(uint32_t*)&g_al[i1] = pack_bf(a2 - bf_hi(a2), a3 - bf_hi(a3));
    }
}

// ---------------- launch ----------------
extern "C" void kernel_launch(void* const* d_in, const int* in_sizes, int n_in,
                              void* d_out, int out_size) {
    const float* x    = (const float*)d_in[0];
    const float* Wqkv = (const float*)d_in[1];
    const float* Wout = (const float*)d_in[2];
    float* out = (float*)d_out;

    cudaFuncSetAttribute(attn_mma_kernel, cudaFuncAttributeMaxDynamicSharedMemorySize, ATT_SMEM);
    cudaFuncSetAttribute(qkv_mma_kernel,  cudaFuncAttributeMaxDynamicSharedMemorySize, MM_SMEM);
    cudaFuncSetAttribute(out_mma_kernel,  cudaFuncAttributeMaxDynamicSharedMemorySize, MM_SMEM);

    __nv_bfloat16 *p_xh, *p_xl, *p_Wqh, *p_Wql, *p_Woh, *p_Wol;
    cudaGetSymbolAddress((void**)&p_xh,  g_xh);
    cudaGetSymbolAddress((void**)&p_xl,  g_xl);
    cudaGetSymbolAddress((void**)&p_Wqh, g_Wqh);
    cudaGetSymbolAddress((void**)&p_Wql, g_Wql);
    cudaGetSymbolAddress((void**)&p_Woh, g_Woh);
    cudaGetSymbolAddress((void**)&p_Wol, g_Wol);

    // x, Wqkv splits
    split4_kernel<<<(ROWS*EMB)/4/256, 256>>>(x, p_xh, p_xl);
    splitT_kernel<<<dim3(QKVN/32, EMB/32), dim3(32,8)>>>(Wqkv, p_Wqh, p_Wql, EMB, QKVN);
    // QKV projection (HMMA)
    qkv_mma_kernel<<<dim3(QKVN/128, ROWS/128), 256, MM_SMEM>>>();
    // RoPE (fp32, in place)
    rope_kernel<<<(ROWS*2*NH*32)/256, 256>>>();
    // tensor-core flash attention (writes bf16 hi/lo attn-out directly)
    attn_mma_kernel<<<dim3(1, SEQ/128, BATCH*NH), 256, ATT_SMEM>>>();
    // output projection (HMMA)
    splitT_kernel<<<dim3(EMB/32, EMB/32), dim3(32,8)>>>(Wout, p_Woh, p_Wol, EMB, EMB);
    out_mma_kernel<<<dim3(EMB/128, ROWS/128), 256, MM_SMEM>>>(out);
}

// round 7
// speedup vs baseline: 2.5411x; 1.1454x over previous
#include <cuda_runtime.h>
#include <cuda_bf16.h>
#include <math.h>
#include <stdint.h>

#define SEQ   2048
#define BATCH 2
#define EMB   1024
#define NH    16
#define HD    64
#define QKVN  (3*EMB)       // 3072
#define ROWS  (BATCH*SEQ)   // 4096

// ---------------- device scratch ----------------
__device__ float g_qkv[ROWS * QKVN];        // [row][3*1024] : q|k|v each [h][d]
__device__ __nv_bfloat16 g_xh[ROWS*EMB],  g_xl[ROWS*EMB];      // x split
__device__ __nv_bfloat16 g_ah[ROWS*EMB],  g_al[ROWS*EMB];      // attn-out split
__device__ __nv_bfloat16 g_Wqh[EMB*QKVN], g_Wql[EMB*QKVN];     // Wqkv^T split [N,K]
__device__ __nv_bfloat16 g_Woh[EMB*EMB],  g_Wol[EMB*EMB];      // Wout^T split [N,K]
// attention operands, per (b,h): q/k [bh][s][d], v transposed [bh][d][s]
__device__ __nv_bfloat16 g_qh[ROWS*EMB], g_ql[ROWS*EMB];
__device__ __nv_bfloat16 g_kh[ROWS*EMB], g_kl[ROWS*EMB];
__device__ __nv_bfloat16 g_vh[ROWS*EMB], g_vl[ROWS*EMB];
__device__ float2 g_rot[SEQ*32];            // (cos, sin) per (s, dim-pair)

// ---------------- helpers ----------------
__device__ __forceinline__ uint32_t smem_u32(const void* p) {
    uint32_t a;
    asm("{ .reg .u64 t; cvta.to.shared.u64 t, %1; cvt.u32.u64 %0, t; }" : "=r"(a) : "l"(p));
    return a;
}
__device__ __forceinline__ void ldsm_x4(uint32_t* r, uint32_t addr) {
    asm volatile("ldmatrix.sync.aligned.m8n8.x4.shared.b16 {%0,%1,%2,%3}, [%4];"
                 : "=r"(r[0]), "=r"(r[1]), "=r"(r[2]), "=r"(r[3]) : "r"(addr));
}
__device__ __forceinline__ void mma_bf16(float* d, const uint32_t* a, const uint32_t* b) {
    asm volatile("mma.sync.aligned.m16n8k16.row.col.f32.bf16.bf16.f32 "
        "{%0,%1,%2,%3}, {%4,%5,%6,%7}, {%8,%9}, {%0,%1,%2,%3};"
        : "+f"(d[0]), "+f"(d[1]), "+f"(d[2]), "+f"(d[3])
        : "r"(a[0]), "r"(a[1]), "r"(a[2]), "r"(a[3]), "r"(b[0]), "r"(b[1]));
}
__device__ __forceinline__ uint32_t pack_bf(float a, float b) {
    __nv_bfloat162 t; t.x = __float2bfloat16(a); t.y = __float2bfloat16(b);
    return *(uint32_t*)&t;
}
__device__ __forceinline__ float bf_hi(float x) {
    return __bfloat162float(__float2bfloat16(x));
}
__device__ __forceinline__ void cpa16(uint32_t dst, const void* src) {
    asm volatile("cp.async.cg.shared.global [%0], [%1], 16;" :: "r"(dst), "l"(src));
}

// ---------------- split conversion kernels ----------------
__device__ __forceinline__ void split1(float x, __nv_bfloat16& h, __nv_bfloat16& l) {
    h = __float2bfloat16(x);
    l = __float2bfloat16(x - __bfloat162float(h));
}

__global__ __launch_bounds__(256) void split4_kernel(const float* __restrict__ in,
                                                     __nv_bfloat16* __restrict__ hi,
                                                     __nv_bfloat16* __restrict__ lo) {
    int i = blockIdx.x * 256 + threadIdx.x;
    float4 v = ((const float4*)in)[i];
    __nv_bfloat16 h0,h1,h2,h3,l0,l1,l2,l3;
    split1(v.x,h0,l0); split1(v.y,h1,l1); split1(v.z,h2,l2); split1(v.w,h3,l3);
    __nv_bfloat162 ph0; ph0.x=h0; ph0.y=h1;
    __nv_bfloat162 ph1; ph1.x=h2; ph1.y=h3;
    __nv_bfloat162 pl0; pl0.x=l0; pl0.y=l1;
    __nv_bfloat162 pl1; pl1.x=l2; pl1.y=l3;
    ((__nv_bfloat162*)hi)[2*i]   = ph0; ((__nv_bfloat162*)hi)[2*i+1] = ph1;
    ((__nv_bfloat162*)lo)[2*i]   = pl0; ((__nv_bfloat162*)lo)[2*i+1] = pl1;
}

// in [K][N] fp32 -> out [N][K] bf16 hi/lo (tiled transpose)
__global__ __launch_bounds__(256) void splitT_kernel(const float* __restrict__ in,
                                                     __nv_bfloat16* __restrict__ hiT,
                                                     __nv_bfloat16* __restrict__ loT,
                                                     int K, int N) {
    __shared__ float t[32][33];
    int n0 = blockIdx.x * 32, k0 = blockIdx.y * 32;
    int tx = threadIdx.x, ty = threadIdx.y;   // block (32,8)
#pragma unroll
    for (int j = 0; j < 4; j++)
        t[ty + j*8][tx] = in[(size_t)(k0 + ty + j*8) * N + n0 + tx];
    __syncthreads();
#pragma unroll
    for (int j = 0; j < 4; j++) {
        int nl = ty + j*8;
        __nv_bfloat16 h, l;
        split1(t[tx][nl], h, l);
        hiT[(size_t)(n0 + nl) * K + k0 + tx] = h;
        loT[(size_t)(n0 + nl) * K + k0 + tx] = l;
    }
}

// ---------------- mma.sync bf16-split GEMM: 256x128 tile, BK=32 ----------------
#define LDSB    80
#define A_T     20480                  // 256 rows * 80
#define B_T     10240                  // 128 rows * 80
#define STAGE_B 61440                  // Ah|Al|Bh|Bl
#define MM_SMEM (2*STAGE_B)            // 122880

template<int NR>
__device__ __forceinline__ void cpa_rows(uint32_t dst, const __nv_bfloat16* __restrict__ g,
                                         int ld, int row0, int k0, int tid) {
#pragma unroll
    for (int l = 0; l < NR/64; l++) {
        int idx = tid + l * 256;
        int r   = idx >> 2;
        int seg = idx & 3;
        cpa16(dst + r*LDSB + seg*16, g + (size_t)(row0 + r) * ld + k0 + seg*8);
    }
}

__device__ __forceinline__ void gemm_mma_body(const __nv_bfloat16* __restrict__ Ah,
                                              const __nv_bfloat16* __restrict__ Al,
                                              const __nv_bfloat16* __restrict__ Bh,
                                              const __nv_bfloat16* __restrict__ Bl,
                                              float* __restrict__ C, int N, int K) {
    extern __shared__ __align__(128) char smem[];
    const uint32_t sb = smem_u32(smem);
    const int tid  = threadIdx.x;
    const int wid  = tid >> 5;
    const int lane = tid & 31;
    const int wm   = wid >> 1;            // 0..3 -> 64-row slice
    const int wn   = wid & 1;             // 0..1 -> 64-col slice
    const int m0   = blockIdx.y * 256;
    const int n0   = blockIdx.x * 128;

    float acc[4][8][4];
#pragma unroll
    for (int mf = 0; mf < 4; mf++)
#pragma unroll
        for (int nf = 0; nf < 8; nf++)
#pragma unroll
            for (int c = 0; c < 4; c++) acc[mf][nf][c] = 0.f;

    const uint32_t aoff = (lane & 15) * LDSB + (lane >> 4) * 16;
    const uint32_t boff = ((lane & 7) + ((lane >> 4) << 3)) * LDSB + (((lane >> 3) & 1) * 16);

    const int NIT = K / 32;

    // prefetch stage 0
    cpa_rows<256>(sb,                 Ah, K, m0, 0, tid);
    cpa_rows<256>(sb + A_T,           Al, K, m0, 0, tid);
    cpa_rows<128>(sb + 2*A_T,         Bh, K, n0, 0, tid);
    cpa_rows<128>(sb + 2*A_T + B_T,   Bl, K, n0, 0, tid);
    asm volatile("cp.async.commit_group;" ::: "memory");

    for (int it = 0; it < NIT; it++) {
        if (it + 1 < NIT) {
            const uint32_t nb = sb + ((it + 1) & 1) * STAGE_B;
            const int k2 = (it + 1) * 32;
            cpa_rows<256>(nb,               Ah, K, m0, k2, tid);
            cpa_rows<256>(nb + A_T,         Al, K, m0, k2, tid);
            cpa_rows<128>(nb + 2*A_T,       Bh, K, n0, k2, tid);
            cpa_rows<128>(nb + 2*A_T + B_T, Bl, K, n0, k2, tid);
            asm volatile("cp.async.commit_group;" ::: "memory");
            asm volatile("cp.async.wait_group 1;" ::: "memory");
        } else {
            asm volatile("cp.async.wait_group 0;" ::: "memory");
        }
        __syncthreads();

        const uint32_t cbs = sb + (it & 1) * STAGE_B;
#pragma unroll
        for (int ks = 0; ks < 2; ks++) {
            const uint32_t kb = ks * 32;
            uint32_t ah[4][4], al[4][4];
#pragma unroll
            for (int mf = 0; mf < 4; mf++) {
                ldsm_x4(ah[mf], cbs +       (wm*64 + mf*16) * LDSB + aoff + kb);
                ldsm_x4(al[mf], cbs + A_T + (wm*64 + mf*16) * LDSB + aoff + kb);
            }
#pragma unroll
            for (int nc = 0; nc < 4; nc++) {
                uint32_t bh[4], bl[4];
                ldsm_x4(bh, cbs + 2*A_T +       (wn*64 + nc*16) * LDSB + boff + kb);
                ldsm_x4(bl, cbs + 2*A_T + B_T + (wn*64 + nc*16) * LDSB + boff + kb);
#pragma unroll
                for (int mf = 0; mf < 4; mf++) {
                    mma_bf16(acc[mf][nc*2],   ah[mf], bh);
                    mma_bf16(acc[mf][nc*2+1], ah[mf], bh + 2);
                    mma_bf16(acc[mf][nc*2],   ah[mf], bl);
                    mma_bf16(acc[mf][nc*2+1], ah[mf], bl + 2);
                    mma_bf16(acc[mf][nc*2],   al[mf], bh);
                    mma_bf16(acc[mf][nc*2+1], al[mf], bh + 2);
                }
            }
        }
        __syncthreads();
    }

    const int r0 = m0 + wm * 64 + (lane >> 2);
    const int c0 = n0 + wn * 64 + (lane & 3) * 2;
#pragma unroll
    for (int mf = 0; mf < 4; mf++)
#pragma unroll
        for (int nf = 0; nf < 8; nf++) {
            const float* a = acc[mf][nf];
            const int r = r0 + mf * 16;
            const int c = c0 + nf * 8;
            *(float2*)&C[(size_t)r * N + c]       = make_float2(a[0], a[1]);
            *(float2*)&C[(size_t)(r + 8) * N + c] = make_float2(a[2], a[3]);
        }
}

__global__ __launch_bounds__(256) void qkv_mma_kernel() {
    gemm_mma_body(g_xh, g_xl, g_Wqh, g_Wql, g_qkv, QKVN, EMB);
}
__global__ __launch_bounds__(256) void out_mma_kernel(float* __restrict__ out) {
    gemm_mma_body(g_ah, g_al, g_Woh, g_Wol, out, EMB, EMB);
}

// ---------------- RoPE cos/sin table ----------------
__global__ __launch_bounds__(256) void rot_kernel() {
    int idx = blockIdx.x * 256 + threadIdx.x;   // SEQ*32
    int s = idx >> 5, i = idx & 31;
    float freq = powf(10000.f, -(float)(2*i) / 64.f);
    float sv, cv;
    sincosf((float)s * freq, &sv, &cv);
    g_rot[idx] = make_float2(cv, sv);
}

// ---------------- prep: rope + bf16 hi/lo split of q,k + transposed v ----------------
// block = 256 threads, handles 64 s-rows of one (b,h)
__global__ __launch_bounds__(256) void qkv_prep_kernel() {
    __shared__ float vt[64][65];
    const int tid = threadIdx.x;
    const int s0  = blockIdx.x * 64;
    const int bh  = blockIdx.y;
    const int b   = bh >> 4, h = bh & 15;
    const size_t inb = (size_t)b * SEQ * QKVN + h * HD;
    const size_t qkb = (size_t)bh * SEQ * HD;

#pragma unroll
    for (int which = 0; which < 2; which++) {
        __nv_bfloat16* hi = which ? g_kh : g_qh;
        __nv_bfloat16* lo = which ? g_kl : g_ql;
#pragma unroll
        for (int l = 0; l < 4; l++) {
            int idx = tid + l * 256;
            int s   = s0 + (idx >> 4);
            int f4  = idx & 15;
            float4 v = *(const float4*)&g_qkv[inb + (size_t)s * QKVN + which*EMB + f4*4];
            float2 cs0 = g_rot[s*32 + f4*2];
            float2 cs1 = g_rot[s*32 + f4*2 + 1];
            float o0 = v.x * cs0.x - v.y * cs0.y;
            float o1 = v.x * cs0.y + v.y * cs0.x;
            float o2 = v.z * cs1.x - v.w * cs1.y;
            float o3 = v.z * cs1.y + v.w * cs1.x;
            if (which == 0) { o0 *= 0.125f; o1 *= 0.125f; o2 *= 0.125f; o3 *= 0.125f; }
            size_t o = qkb + (size_t)s * HD + f4 * 4;
            uint2 ph, pl;
            ph.x = pack_bf(o0, o1); ph.y = pack_bf(o2, o3);
            pl.x = pack_bf(o0 - bf_hi(o0), o1 - bf_hi(o1));
            pl.y = pack_bf(o2 - bf_hi(o2), o3 - bf_hi(o3));
            *(uint2*)&hi[o] = ph;
            *(uint2*)&lo[o] = pl;
        }
    }

    // v: load [s][d], transpose to [d][s] via smem
#pragma unroll
    for (int l = 0; l < 4; l++) {
        int idx = tid + l * 256;
        int sl  = idx >> 4;
        int f4  = idx & 15;
        float4 v = *(const float4*)&g_qkv[inb + (size_t)(s0 + sl) * QKVN + 2*EMB + f4*4];
        vt[f4*4+0][sl] = v.x;
        vt[f4*4+1][sl] = v.y;
        vt[f4*4+2][sl] = v.z;
        vt[f4*4+3][sl] = v.w;
    }
    __syncthreads();
#pragma unroll
    for (int l = 0; l < 4; l++) {
        int idx = tid + l * 256;
        int d   = idx >> 4;
        int sc  = (idx & 15) * 4;
        float a = vt[d][sc], b2 = vt[d][sc+1], c = vt[d][sc+2], e = vt[d][sc+3];
        size_t o = ((size_t)bh * HD + d) * SEQ + s0 + sc;
        uint2 ph, pl;
        ph.x = pack_bf(a, b2); ph.y = pack_bf(c, e);
        pl.x = pack_bf(a - bf_hi(a), b2 - bf_hi(b2));
        pl.y = pack_bf(c - bf_hi(c), e - bf_hi(e));
        *(uint2*)&g_vh[o] = ph;
        *(uint2*)&g_vl[o] = pl;
    }
}

// ---------------- tensor-core flash attention (cp.async pipelined) ----------------
#define AQS    144                      // smem row stride bytes
#define SQH    0
#define SQL    18432
#define SSTG   36864                    // stages start
#define STG_B  36864                    // Kh|Kl|Vh|Vl per stage
#define SKH_O  0
#define SKL_O  9216
#define SVH_O  18432
#define SVL_O  27648
#define ATT_SMEM (SSTG + 2*STG_B)       // 110592

__device__ __forceinline__ void attn_kv_load(uint32_t sbase, size_t qk, size_t vb,
                                             int kt, int tid) {
#pragma unroll
    for (int l = 0; l < 8; l++) {
        int idx = tid + l * 256;        // 0..2047
        int mat = idx >> 9;             // 0:Kh 1:Kl 2:Vh 3:Vl (warp-uniform)
        int r   = (idx >> 3) & 63;
        int c   = idx & 7;
        if (mat == 0)
            cpa16(sbase + SKH_O + r*AQS + c*16, g_kh + qk + (size_t)(kt*64 + r)*HD + c*8);
        else if (mat == 1)
            cpa16(sbase + SKL_O + r*AQS + c*16, g_kl + qk + (size_t)(kt*64 + r)*HD + c*8);
        else if (mat == 2)
            cpa16(sbase + SVH_O + r*AQS + c*16, g_vh + vb + (size_t)r*SEQ + kt*64 + c*8);
        else
            cpa16(sbase + SVL_O + r*AQS + c*16, g_vl + vb + (size_t)r*SEQ + kt*64 + c*8);
    }
}

__global__ __launch_bounds__(256, 2) void attn_mma_kernel() {
    extern __shared__ __align__(128) char sm[];
    const uint32_t sb = smem_u32(sm);
    const int tid  = threadIdx.x;
    const int w    = tid >> 5;
    const int lane = tid & 31;
    const int qt   = 15 - (int)blockIdx.y;      // heavy tiles first
    const int bh   = blockIdx.z;
    const int qbase = qt * 128;
    const size_t qk = (size_t)bh * SEQ * HD;    // q/k [s][d] base
    const size_t vb = (size_t)bh * HD * SEQ;    // v [d][s] base

    // Q tiles (hi+lo) via cp.async
#pragma unroll
    for (int l = 0; l < 8; l++) {
        int idx = tid + l * 256;        // 0..2047
        int mat = idx >> 10;            // 0:hi 1:lo
        int r   = (idx >> 3) & 127;
        int c   = idx & 7;
        const __nv_bfloat16* g = mat ? g_ql : g_qh;
        cpa16(sb + (mat ? SQL : SQH) + r*AQS + c*16, g + qk + (size_t)(qbase + r)*HD + c*8);
    }
    // first K/V tile in the same group
    attn_kv_load(sb + SSTG, qk, vb, 0, tid);
    asm volatile("cp.async.commit_group;" ::: "memory");

    const uint32_t aoff = (lane & 15) * AQS + (lane >> 4) * 16;
    const uint32_t boff = ((lane & 7) + ((lane >> 4) << 3)) * AQS + ((lane >> 3) & 1) * 16;
    const int r0 = qbase + w * 16;

    float o[8][4];
#pragma unroll
    for (int t = 0; t < 8; t++)
#pragma unroll
        for (int c = 0; c < 4; c++) o[t][c] = 0.f;
    float m0r = -1e30f, m1r = -1e30f, l0r = 0.f, l1r = 0.f;

    const int nkt = 2 * qt + 2;
    for (int kt = 0; kt < nkt; kt++) {
        if (kt + 1 < nkt) {
            attn_kv_load(sb + SSTG + ((kt + 1) & 1) * STG_B, qk, vb, kt + 1, tid);
            asm volatile("cp.async.commit_group;" ::: "memory");
            asm volatile("cp.async.wait_group 1;" ::: "memory");
        } else {
            asm volatile("cp.async.wait_group 0;" ::: "memory");
        }
        __syncthreads();

        const uint32_t stg = sb + SSTG + (kt & 1) * STG_B;

        if (kt * 64 <= r0 + 15) {    // tile not fully masked for this warp
            // ---- S = Q K^T (3-term split) ----
            float st[8][4];
#pragma unroll
            for (int t = 0; t < 8; t++)
#pragma unroll
                for (int c = 0; c < 4; c++) st[t][c] = 0.f;

#pragma unroll
            for (int j = 0; j < 4; j++) {
                uint32_t qh[4], ql[4];
                ldsm_x4(qh, sb + SQH + w*16*AQS + aoff + j*32);
                ldsm_x4(ql, sb + SQL + w*16*AQS + aoff + j*32);
#pragma unroll
                for (int nb = 0; nb < 4; nb++) {
                    uint32_t kh[4], kl[4];
                    ldsm_x4(kh, stg + SKH_O + nb*16*AQS + boff + j*32);
                    ldsm_x4(kl, stg + SKL_O + nb*16*AQS + boff + j*32);
                    mma_bf16(st[2*nb],   qh, kh);
                    mma_bf16(st[2*nb+1], qh, kh + 2);
                    mma_bf16(st[2*nb],   qh, kl);
                    mma_bf16(st[2*nb+1], qh, kl + 2);
                    mma_bf16(st[2*nb],   ql, kh);
                    mma_bf16(st[2*nb+1], ql, kh + 2);
                }
            }

            // ---- causal mask ----
            const int rq0 = r0 + (lane >> 2);
            if (kt * 64 + 63 > r0) {
#pragma unroll
                for (int t = 0; t < 8; t++) {
                    int c = kt*64 + t*8 + (lane & 3)*2;
                    if (c     > rq0)     st[t][0] = -1e30f;
                    if (c + 1 > rq0)     st[t][1] = -1e30f;
                    if (c     > rq0 + 8) st[t][2] = -1e30f;
                    if (c + 1 > rq0 + 8) st[t][3] = -1e30f;
                }
            }

            // ---- online softmax ----
            float rm0 = -1e30f, rm1 = -1e30f;
#pragma unroll
            for (int t = 0; t < 8; t++) {
                rm0 = fmaxf(rm0, fmaxf(st[t][0], st[t][1]));
                rm1 = fmaxf(rm1, fmaxf(st[t][2], st[t][3]));
            }
            rm0 = fmaxf(rm0, __shfl_xor_sync(0xffffffffu, rm0, 1));
            rm0 = fmaxf(rm0, __shfl_xor_sync(0xffffffffu, rm0, 2));
            rm1 = fmaxf(rm1, __shfl_xor_sync(0xffffffffu, rm1, 1));
            rm1 = fmaxf(rm1, __shfl_xor_sync(0xffffffffu, rm1, 2));
            float mn0 = fmaxf(m0r, rm0), mn1 = fmaxf(m1r, rm1);
            float al0 = __expf(m0r - mn0), al1 = __expf(m1r - mn1);
            float rs0 = 0.f, rs1 = 0.f;
#pragma unroll
            for (int t = 0; t < 8; t++) {
                st[t][0] = __expf(st[t][0] - mn0);
                st[t][1] = __expf(st[t][1] - mn0);
                st[t][2] = __expf(st[t][2] - mn1);
                st[t][3] = __expf(st[t][3] - mn1);
                rs0 += st[t][0] + st[t][1];
                rs1 += st[t][2] + st[t][3];
            }
            rs0 += __shfl_xor_sync(0xffffffffu, rs0, 1);
            rs0 += __shfl_xor_sync(0xffffffffu, rs0, 2);
            rs1 += __shfl_xor_sync(0xffffffffu, rs1, 1);
            rs1 += __shfl_xor_sync(0xffffffffu, rs1, 2);
            l0r = l0r * al0 + rs0;
            l1r = l1r * al1 + rs1;
            m0r = mn0; m1r = mn1;
#pragma unroll
            for (int t = 0; t < 8; t++) {
                o[t][0] *= al0; o[t][1] *= al0;
                o[t][2] *= al1; o[t][3] *= al1;
            }

            // ---- O += P V (3-term split) ----
#pragma unroll
            for (int j = 0; j < 4; j++) {
                float p00 = st[2*j][0],   p01 = st[2*j][1];
                float p10 = st[2*j][2],   p11 = st[2*j][3];
                float q00 = st[2*j+1][0], q01 = st[2*j+1][1];
                float q10 = st[2*j+1][2], q11 = st[2*j+1][3];
                uint32_t ph[4], pl[4];
                ph[0] = pack_bf(p00, p01); ph[1] = pack_bf(p10, p11);
                ph[2] = pack_bf(q00, q01); ph[3] = pack_bf(q10, q11);
                pl[0] = pack_bf(p00 - bf_hi(p00), p01 - bf_hi(p01));
                pl[1] = pack_bf(p10 - bf_hi(p10), p11 - bf_hi(p11));
                pl[2] = pack_bf(q00 - bf_hi(q00), q01 - bf_hi(q01));
                pl[3] = pack_bf(q10 - bf_hi(q10), q11 - bf_hi(q11));
#pragma unroll
                for (int db = 0; db < 4; db++) {
                    uint32_t vh[4], vl[4];
                    ldsm_x4(vh, stg + SVH_O + db*16*AQS + boff + j*32);
                    ldsm_x4(vl, stg + SVL_O + db*16*AQS + boff + j*32);
                    mma_bf16(o[2*db],   ph, vh);
                    mma_bf16(o[2*db+1], ph, vh + 2);
                    mma_bf16(o[2*db],   ph, vl);
                    mma_bf16(o[2*db+1], ph, vl + 2);
                    mma_bf16(o[2*db],   pl, vh);
                    mma_bf16(o[2*db+1], pl, vh + 2);
                }
            }
        }
        __syncthreads();
    }

    // ---- epilogue: normalize, split to bf16 hi/lo, write g_ah/g_al ----
    const int b = bh >> 4, h = bh & 15;
    const float inv0 = 1.f / l0r, inv1 = 1.f / l1r;
    const int rq0 = qbase + w*16 + (lane >> 2);
#pragma unroll
    for (int t = 0; t < 8; t++) {
        int col = h * HD + t*8 + (lane & 3) * 2;
        float a0 = o[t][0] * inv0, a1 = o[t][1] * inv0;
        float a2 = o[t][2] * inv1, a3 = o[t][3] * inv1;
        size_t i0 = ((size_t)b*SEQ + rq0)     * EMB + col;
        size_t i1 = ((size_t)b*SEQ + rq0 + 8) * EMB + col;
        *(uint32_t*)&g_ah[i0] = pack_bf(a0, a1);
        *(uint32_t*)&g_al[i0] = pack_bf(a0 - bf_hi(a0), a1 - bf_hi(a1));
        *(uint32_t*)&g_ah[i1] = pack_bf(a2, a3);
        *(uint32_t*)&g_al[i1] = pack_bf(a2 - bf_hi(a2), a3 - bf_hi(a3));
    }
}

// ---------------- launch ----------------
extern "C" void kernel_launch(void* const* d_in, const int* in_sizes, int n_in,
                              void* d_out, int out_size) {
    const float* x    = (const float*)d_in[0];
    const float* Wqkv = (const float*)d_in[1];
    const float* Wout = (const float*)d_in[2];
    float* out = (float*)d_out;

    cudaFuncSetAttribute(attn_mma_kernel, cudaFuncAttributeMaxDynamicSharedMemorySize, ATT_SMEM);
    cudaFuncSetAttribute(qkv_mma_kernel,  cudaFuncAttributeMaxDynamicSharedMemorySize, MM_SMEM);
    cudaFuncSetAttribute(out_mma_kernel,  cudaFuncAttributeMaxDynamicSharedMemorySize, MM_SMEM);

    __nv_bfloat16 *p_xh, *p_xl, *p_Wqh, *p_Wql, *p_Woh, *p_Wol;
    cudaGetSymbolAddress((void**)&p_xh,  g_xh);
    cudaGetSymbolAddress((void**)&p_xl,  g_xl);
    cudaGetSymbolAddress((void**)&p_Wqh, g_Wqh);
    cudaGetSymbolAddress((void**)&p_Wql, g_Wql);
    cudaGetSymbolAddress((void**)&p_Woh, g_Woh);
    cudaGetSymbolAddress((void**)&p_Wol, g_Wol);

    // x, Wqkv splits
    split4_kernel<<<(ROWS*EMB)/4/256, 256>>>(x, p_xh, p_xl);
    splitT_kernel<<<dim3(QKVN/32, EMB/32), dim3(32,8)>>>(Wqkv, p_Wqh, p_Wql, EMB, QKVN);
    // QKV projection (HMMA, 256x128 tile)
    qkv_mma_kernel<<<dim3(QKVN/128, ROWS/256), 256, MM_SMEM>>>();
    // RoPE table + prep (rope, bf16 split, V transpose)
    rot_kernel<<<(SEQ*32)/256, 256>>>();
    qkv_prep_kernel<<<dim3(SEQ/64, BATCH*NH), 256>>>();
    // tensor-core flash attention
    attn_mma_kernel<<<dim3(1, SEQ/128, BATCH*NH), 256, ATT_SMEM>>>();
    // output projection (HMMA, 256x128 tile)
    splitT_kernel<<<dim3(EMB/32, EMB/32), dim3(32,8)>>>(Wout, p_Woh, p_Wol, EMB, EMB);
    out_mma_kernel<<<dim3(EMB/128, ROWS/256), 256, MM_SMEM>>>(out);
}

// round 9
// speedup vs baseline: 3.5720x; 1.4057x over previous
#include <cuda_runtime.h>
#include <cuda_fp16.h>
#include <math.h>
#include <stdint.h>

#define SEQ   2048
#define BATCH 2
#define EMB   1024
#define NH    16
#define HD    64
#define QKVN  (3*EMB)       // 3072
#define ROWS  (BATCH*SEQ)   // 4096

// ---------------- device scratch ----------------
__device__ float g_qkv[ROWS * QKVN];        // [row][3*1024] : q|k|v each [h][d]
__device__ __half g_xh[ROWS*EMB],  g_xl[ROWS*EMB];      // x 2-term split
__device__ __half g_ah[ROWS*EMB],  g_al[ROWS*EMB];      // attn-out 2-term split
__device__ __half g_Wqh[EMB*QKVN];                      // Wqkv^T single fp16 [N,K]
__device__ __half g_Woh[EMB*EMB];                       // Wout^T single fp16 [N,K]
// attention operands per (b,h): q 2-term, k/v single; v transposed [bh][d][s]
__device__ __half g_qh[ROWS*EMB], g_ql[ROWS*EMB];
__device__ __half g_kh[ROWS*EMB];
__device__ __half g_vh[ROWS*EMB];
__device__ float2 g_rot[SEQ*32];            // (cos, sin) per (s, dim-pair)

// ---------------- helpers ----------------
__device__ __forceinline__ uint32_t smem_u32(const void* p) {
    uint32_t a;
    asm("{ .reg .u64 t; cvta.to.shared.u64 t, %1; cvt.u32.u64 %0, t; }" : "=r"(a) : "l"(p));
    return a;
}
__device__ __forceinline__ void ldsm_x4(uint32_t* r, uint32_t addr) {
    asm volatile("ldmatrix.sync.aligned.m8n8.x4.shared.b16 {%0,%1,%2,%3}, [%4];"
                 : "=r"(r[0]), "=r"(r[1]), "=r"(r[2]), "=r"(r[3]) : "r"(addr));
}
__device__ __forceinline__ void mma_f16(float* d, const uint32_t* a, const uint32_t* b) {
    asm volatile("mma.sync.aligned.m16n8k16.row.col.f32.f16.f16.f32 "
        "{%0,%1,%2,%3}, {%4,%5,%6,%7}, {%8,%9}, {%0,%1,%2,%3};"
        : "+f"(d[0]), "+f"(d[1]), "+f"(d[2]), "+f"(d[3])
        : "r"(a[0]), "r"(a[1]), "r"(a[2]), "r"(a[3]), "r"(b[0]), "r"(b[1]));
}
__device__ __forceinline__ uint32_t pack_hf(float a, float b) {
    __half2 t = __floats2half2_rn(a, b);
    return *(uint32_t*)&t;
}
__device__ __forceinline__ float hf_hi(float x) {
    return __half2float(__float2half(x));
}
__device__ __forceinline__ void cpa16(uint32_t dst, const void* src) {
    asm volatile("cp.async.cg.shared.global [%0], [%1], 16;" :: "r"(dst), "l"(src));
}

// ---------------- split / transpose conversion kernels ----------------
__global__ __launch_bounds__(256) void split4_kernel(const float* __restrict__ in,
                                                     __half* __restrict__ hi,
                                                     __half* __restrict__ lo) {
    int i = blockIdx.x * 256 + threadIdx.x;
    float4 v = ((const float4*)in)[i];
    float h0 = hf_hi(v.x), h1 = hf_hi(v.y), h2 = hf_hi(v.z), h3 = hf_hi(v.w);
    ((uint32_t*)hi)[2*i]   = pack_hf(v.x, v.y);
    ((uint32_t*)hi)[2*i+1] = pack_hf(v.z, v.w);
    ((uint32_t*)lo)[2*i]   = pack_hf(v.x - h0, v.y - h1);
    ((uint32_t*)lo)[2*i+1] = pack_hf(v.z - h2, v.w - h3);
}

// in [K][N] fp32 -> out [N][K] single fp16 (tiled transpose)
__global__ __launch_bounds__(256) void splitTh_kernel(const float* __restrict__ in,
                                                      __half* __restrict__ hiT,
                                                      int K, int N) {
    __shared__ float t[32][33];
    int n0 = blockIdx.x * 32, k0 = blockIdx.y * 32;
    int tx = threadIdx.x, ty = threadIdx.y;   // block (32,8)
#pragma unroll
    for (int j = 0; j < 4; j++)
        t[ty + j*8][tx] = in[(size_t)(k0 + ty + j*8) * N + n0 + tx];
    __syncthreads();
#pragma unroll
    for (int j = 0; j < 4; j++) {
        int nl = ty + j*8;
        hiT[(size_t)(n0 + nl) * K + k0 + tx] = __float2half(t[tx][nl]);
    }
}

// ---------------- fp16 2-term GEMM: 256x128 tile, BK=32 ----------------
#define LDSB    80
#define A_T     20480                  // 256 rows * 80
#define B_T     10240                  // 128 rows * 80
#define STAGE_B (2*A_T + B_T)          // 51200 : Ah|Al|Bh
#define MM_SMEM (2*STAGE_B)            // 102400

template<int NR>
__device__ __forceinline__ void cpa_rows(uint32_t dst, const __half* __restrict__ g,
                                         int ld, int row0, int k0, int tid) {
#pragma unroll
    for (int l = 0; l < NR/64; l++) {
        int idx = tid + l * 256;
        int r   = idx >> 2;
        int seg = idx & 3;
        cpa16(dst + r*LDSB + seg*16, g + (size_t)(row0 + r) * ld + k0 + seg*8);
    }
}

__device__ __forceinline__ void gemm2_body(const __half* __restrict__ Ah,
                                           const __half* __restrict__ Al,
                                           const __half* __restrict__ Bh,
                                           float* __restrict__ C, int N, int K) {
    extern __shared__ __align__(128) char smem[];
    const uint32_t sb = smem_u32(smem);
    const int tid  = threadIdx.x;
    const int wid  = tid >> 5;
    const int lane = tid & 31;
    const int wm   = wid >> 1;            // 0..3 -> 64-row slice
    const int wn   = wid & 1;             // 0..1 -> 64-col slice
    const int m0   = blockIdx.y * 256;
    const int n0   = blockIdx.x * 128;

    float acc[4][8][4];
#pragma unroll
    for (int mf = 0; mf < 4; mf++)
#pragma unroll
        for (int nf = 0; nf < 8; nf++)
#pragma unroll
            for (int c = 0; c < 4; c++) acc[mf][nf][c] = 0.f;

    const uint32_t aoff = (lane & 15) * LDSB + (lane >> 4) * 16;
    const uint32_t boff = ((lane & 7) + ((lane >> 4) << 3)) * LDSB + (((lane >> 3) & 1) * 16);

    const int NIT = K / 32;

    cpa_rows<256>(sb,           Ah, K, m0, 0, tid);
    cpa_rows<256>(sb + A_T,     Al, K, m0, 0, tid);
    cpa_rows<128>(sb + 2*A_T,   Bh, K, n0, 0, tid);
    asm volatile("cp.async.commit_group;" ::: "memory");

    for (int it = 0; it < NIT; it++) {
        if (it + 1 < NIT) {
            const uint32_t nb = sb + ((it + 1) & 1) * STAGE_B;
            const int k2 = (it + 1) * 32;
            cpa_rows<256>(nb,         Ah, K, m0, k2, tid);
            cpa_rows<256>(nb + A_T,   Al, K, m0, k2, tid);
            cpa_rows<128>(nb + 2*A_T, Bh, K, n0, k2, tid);
            asm volatile("cp.async.commit_group;" ::: "memory");
            asm volatile("cp.async.wait_group 1;" ::: "memory");
        } else {
            asm volatile("cp.async.wait_group 0;" ::: "memory");
        }
        __syncthreads();

        const uint32_t cbs = sb + (it & 1) * STAGE_B;
#pragma unroll
        for (int ks = 0; ks < 2; ks++) {
            const uint32_t kb = ks * 32;
            uint32_t ah[4][4], al[4][4];
#pragma unroll
            for (int mf = 0; mf < 4; mf++) {
                ldsm_x4(ah[mf], cbs +       (wm*64 + mf*16) * LDSB + aoff + kb);
                ldsm_x4(al[mf], cbs + A_T + (wm*64 + mf*16) * LDSB + aoff + kb);
            }
#pragma unroll
            for (int nc = 0; nc < 4; nc++) {
                uint32_t bh[4];
                ldsm_x4(bh, cbs + 2*A_T + (wn*64 + nc*16) * LDSB + boff + kb);
#pragma unroll
                for (int mf = 0; mf < 4; mf++) {
                    mma_f16(acc[mf][nc*2],   ah[mf], bh);
                    mma_f16(acc[mf][nc*2+1], ah[mf], bh + 2);
                    mma_f16(acc[mf][nc*2],   al[mf], bh);
                    mma_f16(acc[mf][nc*2+1], al[mf], bh + 2);
                }
            }
        }
        __syncthreads();
    }

    const int r0 = m0 + wm * 64 + (lane >> 2);
    const int c0 = n0 + wn * 64 + (lane & 3) * 2;
#pragma unroll
    for (int mf = 0; mf < 4; mf++)
#pragma unroll
        for (int nf = 0; nf < 8; nf++) {
            const float* a = acc[mf][nf];
            const int r = r0 + mf * 16;
            const int c = c0 + nf * 8;
            *(float2*)&C[(size_t)r * N + c]       = make_float2(a[0], a[1]);
            *(float2*)&C[(size_t)(r + 8) * N + c] = make_float2(a[2], a[3]);
        }
}

__global__ __launch_bounds__(256) void qkv_mma_kernel() {
    gemm2_body(g_xh, g_xl, g_Wqh, g_qkv, QKVN, EMB);
}
__global__ __launch_bounds__(256) void out_mma_kernel(float* __restrict__ out) {
    gemm2_body(g_ah, g_al, g_Woh, out, EMB, EMB);
}

// ---------------- RoPE cos/sin table ----------------
__global__ __launch_bounds__(256) void rot_kernel() {
    int idx = blockIdx.x * 256 + threadIdx.x;   // SEQ*32
    int s = idx >> 5, i = idx & 31;
    float freq = powf(10000.f, -(float)(2*i) / 64.f);
    float sv, cv;
    sincosf((float)s * freq, &sv, &cv);
    g_rot[idx] = make_float2(cv, sv);
}

// ---------------- prep: rope + fp16 ops for attention ----------------
// block = 256 threads, 64 s-rows of one (b,h)
__global__ __launch_bounds__(256) void qkv_prep_kernel() {
    __shared__ float vt[64][65];
    const int tid = threadIdx.x;
    const int s0  = blockIdx.x * 64;
    const int bh  = blockIdx.y;
    const int b   = bh >> 4, h = bh & 15;
    const size_t inb = (size_t)b * SEQ * QKVN + h * HD;
    const size_t qkb = (size_t)bh * SEQ * HD;

    // q: rope + scale + 2-term split
#pragma unroll
    for (int l = 0; l < 4; l++) {
        int idx = tid + l * 256;
        int s   = s0 + (idx >> 4);
        int f4  = idx & 15;
        float4 v = *(const float4*)&g_qkv[inb + (size_t)s * QKVN + f4*4];
        float2 cs0 = g_rot[s*32 + f4*2];
        float2 cs1 = g_rot[s*32 + f4*2 + 1];
        float o0 = (v.x * cs0.x - v.y * cs0.y) * 0.125f;
        float o1 = (v.x * cs0.y + v.y * cs0.x) * 0.125f;
        float o2 = (v.z * cs1.x - v.w * cs1.y) * 0.125f;
        float o3 = (v.z * cs1.y + v.w * cs1.x) * 0.125f;
        size_t o = qkb + (size_t)s * HD + f4 * 4;
        uint2 ph, pl;
        ph.x = pack_hf(o0, o1); ph.y = pack_hf(o2, o3);
        pl.x = pack_hf(o0 - hf_hi(o0), o1 - hf_hi(o1));
        pl.y = pack_hf(o2 - hf_hi(o2), o3 - hf_hi(o3));
        *(uint2*)&g_qh[o] = ph;
        *(uint2*)&g_ql[o] = pl;
    }
    // k: rope, single fp16
#pragma unroll
    for (int l = 0; l < 4; l++) {
        int idx = tid + l * 256;
        int s   = s0 + (idx >> 4);
        int f4  = idx & 15;
        float4 v = *(const float4*)&g_qkv[inb + (size_t)s * QKVN + EMB + f4*4];
        float2 cs0 = g_rot[s*32 + f4*2];
        float2 cs1 = g_rot[s*32 + f4*2 + 1];
        float o0 = v.x * cs0.x - v.y * cs0.y;
        float o1 = v.x * cs0.y + v.y * cs0.x;
        float o2 = v.z * cs1.x - v.w * cs1.y;
        float o3 = v.z * cs1.y + v.w * cs1.x;
        size_t o = qkb + (size_t)s * HD + f4 * 4;
        uint2 ph;
        ph.x = pack_hf(o0, o1); ph.y = pack_hf(o2, o3);
        *(uint2*)&g_kh[o] = ph;
    }
    // v: transpose to [d][s], single fp16
#pragma unroll
    for (int l = 0; l < 4; l++) {
        int idx = tid + l * 256;
        int sl  = idx >> 4;
        int f4  = idx & 15;
        float4 v = *(const float4*)&g_qkv[inb + (size_t)(s0 + sl) * QKVN + 2*EMB + f4*4];
        vt[f4*4+0][sl] = v.x;
        vt[f4*4+1][sl] = v.y;
        vt[f4*4+2][sl] = v.z;
        vt[f4*4+3][sl] = v.w;
    }
    __syncthreads();
#pragma unroll
    for (int l = 0; l < 4; l++) {
        int idx = tid + l * 256;
        int d   = idx >> 4;
        int sc  = (idx & 15) * 4;
        size_t o = ((size_t)bh * HD + d) * SEQ + s0 + sc;
        uint2 ph;
        ph.x = pack_hf(vt[d][sc],   vt[d][sc+1]);
        ph.y = pack_hf(vt[d][sc+2], vt[d][sc+3]);
        *(uint2*)&g_vh[o] = ph;
    }
}

// ---------------- fp16 tensor-core flash attention ----------------
#define AQS    144                      // smem row stride bytes
#define SQH    0
#define SQL    18432
#define SSTG   36864                    // stages start
#define STG_B  18432                    // Kh|Vh per stage
#define SKH_O  0
#define SVH_O  9216
#define ATT_SMEM (SSTG + 2*STG_B)       // 73728

__device__ __forceinline__ void attn_kv_load(uint32_t sbase, size_t qk, size_t vb,
                                             int kt, int tid) {
#pragma unroll
    for (int l = 0; l < 4; l++) {
        int idx = tid + l * 256;        // 0..1023
        int mat = idx >> 9;             // 0:Kh 1:Vh (warp-uniform)
        int r   = (idx >> 3) & 63;
        int c   = idx & 7;
        if (mat == 0)
            cpa16(sbase + SKH_O + r*AQS + c*16, g_kh + qk + (size_t)(kt*64 + r)*HD + c*8);
        else
            cpa16(sbase + SVH_O + r*AQS + c*16, g_vh + vb + (size_t)r*SEQ + kt*64 + c*8);
    }
}

__global__ __launch_bounds__(256, 2) void attn_mma_kernel() {
    extern __shared__ __align__(128) char sm[];
    const uint32_t sb = smem_u32(sm);
    const int tid  = threadIdx.x;
    const int w    = tid >> 5;
    const int lane = tid & 31;
    const int qt   = 15 - (int)blockIdx.y;      // heavy tiles first
    const int bh   = blockIdx.z;
    const int qbase = qt * 128;
    const size_t qk = (size_t)bh * SEQ * HD;    // q/k [s][d] base
    const size_t vb = (size_t)bh * HD * SEQ;    // v [d][s] base

    // Q tiles (hi+lo) via cp.async
#pragma unroll
    for (int l = 0; l < 8; l++) {
        int idx = tid + l * 256;        // 0..2047
        int mat = idx >> 10;            // 0:hi 1:lo
        int r   = (idx >> 3) & 127;
        int c   = idx & 7;
        const __half* g = mat ? g_ql : g_qh;
        cpa16(sb + (mat ? SQL : SQH) + r*AQS + c*16, g + qk + (size_t)(qbase + r)*HD + c*8);
    }
    attn_kv_load(sb + SSTG, qk, vb, 0, tid);
    asm volatile("cp.async.commit_group;" ::: "memory");

    const uint32_t aoff = (lane & 15) * AQS + (lane >> 4) * 16;
    const uint32_t boff = ((lane & 7) + ((lane >> 4) << 3)) * AQS + ((lane >> 3) & 1) * 16;
    const int r0 = qbase + w * 16;

    float o[8][4];
#pragma unroll
    for (int t = 0; t < 8; t++)
#pragma unroll
        for (int c = 0; c < 4; c++) o[t][c] = 0.f;
    float m0r = -1e30f, m1r = -1e30f, l0r = 0.f, l1r = 0.f;

    const int nkt = 2 * qt + 2;
    for (int kt = 0; kt < nkt; kt++) {
        if (kt + 1 < nkt) {
            attn_kv_load(sb + SSTG + ((kt + 1) & 1) * STG_B, qk, vb, kt + 1, tid);
            asm volatile("cp.async.commit_group;" ::: "memory");
            asm volatile("cp.async.wait_group 1;" ::: "memory");
        } else {
            asm volatile("cp.async.wait_group 0;" ::: "memory");
        }
        __syncthreads();

        const uint32_t stg = sb + SSTG + (kt & 1) * STG_B;

        if (kt * 64 <= r0 + 15) {    // tile not fully masked for this warp
            // ---- S = Q K^T (2-term: Qh*K + Ql*K) ----
            float st[8][4];
#pragma unroll
            for (int t = 0; t < 8; t++)
#pragma unroll
                for (int c = 0; c < 4; c++) st[t][c] = 0.f;

#pragma unroll
            for (int j = 0; j < 4; j++) {
                uint32_t qh[4], ql[4];
                ldsm_x4(qh, sb + SQH + w*16*AQS + aoff + j*32);
                ldsm_x4(ql, sb + SQL + w*16*AQS + aoff + j*32);
#pragma unroll
                for (int nb = 0; nb < 4; nb++) {
                    uint32_t kh[4];
                    ldsm_x4(kh, stg + SKH_O + nb*16*AQS + boff + j*32);
                    mma_f16(st[2*nb],   qh, kh);
                    mma_f16(st[2*nb+1], qh, kh + 2);
                    mma_f16(st[2*nb],   ql, kh);
                    mma_f16(st[2*nb+1], ql, kh + 2);
                }
            }

            // ---- causal mask ----
            const int rq0 = r0 + (lane >> 2);
            if (kt * 64 + 63 > r0) {
#pragma unroll
                for (int t = 0; t < 8; t++) {
                    int c = kt*64 + t*8 + (lane & 3)*2;
                    if (c     > rq0)     st[t][0] = -1e30f;
                    if (c + 1 > rq0)     st[t][1] = -1e30f;
                    if (c     > rq0 + 8) st[t][2] = -1e30f;
                    if (c + 1 > rq0 + 8) st[t][3] = -1e30f;
                }
            }

            // ---- online softmax ----
            float rm0 = -1e30f, rm1 = -1e30f;
#pragma unroll
            for (int t = 0; t < 8; t++) {
                rm0 = fmaxf(rm0, fmaxf(st[t][0], st[t][1]));
                rm1 = fmaxf(rm1, fmaxf(st[t][2], st[t][3]));
            }
            rm0 = fmaxf(rm0, __shfl_xor_sync(0xffffffffu, rm0, 1));
            rm0 = fmaxf(rm0, __shfl_xor_sync(0xffffffffu, rm0, 2));
            rm1 = fmaxf(rm1, __shfl_xor_sync(0xffffffffu, rm1, 1));
            rm1 = fmaxf(rm1, __shfl_xor_sync(0xffffffffu, rm1, 2));
            float mn0 = fmaxf(m0r, rm0), mn1 = fmaxf(m1r, rm1);
            float al0 = __expf(m0r - mn0), al1 = __expf(m1r - mn1);
            float rs0 = 0.f, rs1 = 0.f;
#pragma unroll
            for (int t = 0; t < 8; t++) {
                st[t][0] = __expf(st[t][0] - mn0);
                st[t][1] = __expf(st[t][1] - mn0);
                st[t][2] = __expf(st[t][2] - mn1);
                st[t][3] = __expf(st[t][3] - mn1);
                rs0 += st[t][0] + st[t][1];
                rs1 += st[t][2] + st[t][3];
            }
            rs0 += __shfl_xor_sync(0xffffffffu, rs0, 1);
            rs0 += __shfl_xor_sync(0xffffffffu, rs0, 2);
            rs1 += __shfl_xor_sync(0xffffffffu, rs1, 1);
            rs1 += __shfl_xor_sync(0xffffffffu, rs1, 2);
            l0r = l0r * al0 + rs0;
            l1r = l1r * al1 + rs1;
            m0r = mn0; m1r = mn1;
#pragma unroll
            for (int t = 0; t < 8; t++) {
                o[t][0] *= al0; o[t][1] *= al0;
                o[t][2] *= al1; o[t][3] *= al1;
            }

            // ---- O += P V (2-term: Ph*V + Pl*V) ----
#pragma unroll
            for (int j = 0; j < 4; j++) {
                float p00 = st[2*j][0],   p01 = st[2*j][1];
                float p10 = st[2*j][2],   p11 = st[2*j][3];
                float q00 = st[2*j+1][0], q01 = st[2*j+1][1];
                float q10 = st[2*j+1][2], q11 = st[2*j+1][3];
                uint32_t ph[4], pl[4];
                ph[0] = pack_hf(p00, p01); ph[1] = pack_hf(p10, p11);
                ph[2] = pack_hf(q00, q01); ph[3] = pack_hf(q10, q11);
                pl[0] = pack_hf(p00 - hf_hi(p00), p01 - hf_hi(p01));
                pl[1] = pack_hf(p10 - hf_hi(p10), p11 - hf_hi(p11));
                pl[2] = pack_hf(q00 - hf_hi(q00), q01 - hf_hi(q01));
                pl[3] = pack_hf(q10 - hf_hi(q10), q11 - hf_hi(q11));
#pragma unroll
                for (int db = 0; db < 4; db++) {
                    uint32_t vh[4];
                    ldsm_x4(vh, stg + SVH_O + db*16*AQS + boff + j*32);
                    mma_f16(o[2*db],   ph, vh);
                    mma_f16(o[2*db+1], ph, vh + 2);
                    mma_f16(o[2*db],   pl, vh);
                    mma_f16(o[2*db+1], pl, vh + 2);
                }
            }
        }
        __syncthreads();
    }

    // ---- epilogue: normalize, 2-term fp16 split, write g_ah/g_al ----
    const int b = bh >> 4, h = bh & 15;
    const float inv0 = 1.f / l0r, inv1 = 1.f / l1r;
    const int rq0 = qbase + w*16 + (lane >> 2);
#pragma unroll
    for (int t = 0; t < 8; t++) {
        int col = h * HD + t*8 + (lane & 3) * 2;
        float a0 = o[t][0] * inv0, a1 = o[t][1] * inv0;
        float a2 = o[t][2] * inv1, a3 = o[t][3] * inv1;
        size_t i0 = ((size_t)b*SEQ + rq0)     * EMB + col;
        size_t i1 = ((size_t)b*SEQ + rq0 + 8) * EMB + col;
        *(uint32_t*)&g_ah[i0] = pack_hf(a0, a1);
        *(uint32_t*)&g_al[i0] = pack_hf(a0 - hf_hi(a0), a1 - hf_hi(a1));
        *(uint32_t*)&g_ah[i1] = pack_hf(a2, a3);
        *(uint32_t*)&g_al[i1] = pack_hf(a2 - hf_hi(a2), a3 - hf_hi(a3));
    }
}

// ---------------- launch ----------------
extern "C" void kernel_launch(void* const* d_in, const int* in_sizes, int n_in,
                              void* d_out, int out_size) {
    const float* x    = (const float*)d_in[0];
    const float* Wqkv = (const float*)d_in[1];
    const float* Wout = (const float*)d_in[2];
    float* out = (float*)d_out;

    cudaFuncSetAttribute(attn_mma_kernel, cudaFuncAttributeMaxDynamicSharedMemorySize, ATT_SMEM);
    cudaFuncSetAttribute(qkv_mma_kernel,  cudaFuncAttributeMaxDynamicSharedMemorySize, MM_SMEM);
    cudaFuncSetAttribute(out_mma_kernel,  cudaFuncAttributeMaxDynamicSharedMemorySize, MM_SMEM);

    __half *p_xh, *p_xl, *p_Wqh, *p_Woh;
    cudaGetSymbolAddress((void**)&p_xh,  g_xh);
    cudaGetSymbolAddress((void**)&p_xl,  g_xl);
    cudaGetSymbolAddress((void**)&p_Wqh, g_Wqh);
    cudaGetSymbolAddress((void**)&p_Woh, g_Woh);

    // x 2-term split, Wqkv^T single fp16
    split4_kernel<<<(ROWS*EMB)/4/256, 256>>>(x, p_xh, p_xl);
    splitTh_kernel<<<dim3(QKVN/32, EMB/32), dim3(32,8)>>>(Wqkv, p_Wqh, EMB, QKVN);
    // QKV projection (fp16 2-term HMMA)
    qkv_mma_kernel<<<dim3(QKVN/128, ROWS/256), 256, MM_SMEM>>>();
    // RoPE table + prep
    rot_kernel<<<(SEQ*32)/256, 256>>>();
    qkv_prep_kernel<<<dim3(SEQ/64, BATCH*NH), 256>>>();
    // fp16 tensor-core flash attention
    attn_mma_kernel<<<dim3(1, SEQ/128, BATCH*NH), 256, ATT_SMEM>>>();
    // output projection (fp16 2-term HMMA)
    splitTh_kernel<<<dim3(EMB/32, EMB/32), dim3(32,8)>>>(Wout, p_Woh, EMB, EMB);
    out_mma_kernel<<<dim3(EMB/128, ROWS/256), 256, MM_SMEM>>>(out);
}

// round 14
// speedup vs baseline: 5.6054x; 1.5692x over previous
#include <cuda_runtime.h>
#include <cuda_fp16.h>
#include <math.h>
#include <stdint.h>

#define SEQ   2048
#define BATCH 2
#define EMB   1024
#define NH    16
#define HD    64
#define QKVN  (3*EMB)       // 3072
#define ROWS  (BATCH*SEQ)   // 4096

// ---------------- device scratch ----------------
__device__ float g_qkv[ROWS * QKVN];        // [row][3*1024] : q|k|v each [h][d]
__device__ __half g_x[ROWS*EMB];            // x fp16
__device__ __half g_a[ROWS*EMB];            // attn-out fp16
__device__ __half g_Wq[EMB*QKVN];           // Wqkv^T fp16 [N,K]
__device__ __half g_Wo[EMB*EMB];            // Wout^T fp16 [N,K]
// attention operands per (b,h): q/k [bh][s][d], v transposed [bh][d][s]
__device__ __half g_q[ROWS*EMB];
__device__ __half g_k[ROWS*EMB];
__device__ __half g_v[ROWS*EMB];
__device__ float2 g_rot[SEQ*32];            // (cos, sin) per (s, dim-pair)

// ---------------- helpers ----------------
__device__ __forceinline__ uint32_t smem_u32(const void* p) {
    uint32_t a;
    asm("{ .reg .u64 t; cvta.to.shared.u64 t, %1; cvt.u32.u64 %0, t; }" : "=r"(a) : "l"(p));
    return a;
}
__device__ __forceinline__ void ldsm_x4(uint32_t* r, uint32_t addr) {
    asm volatile("ldmatrix.sync.aligned.m8n8.x4.shared.b16 {%0,%1,%2,%3}, [%4];"
                 : "=r"(r[0]), "=r"(r[1]), "=r"(r[2]), "=r"(r[3]) : "r"(addr));
}
__device__ __forceinline__ void mma_f16(float* d, const uint32_t* a, const uint32_t* b) {
    asm volatile("mma.sync.aligned.m16n8k16.row.col.f32.f16.f16.f32 "
        "{%0,%1,%2,%3}, {%4,%5,%6,%7}, {%8,%9}, {%0,%1,%2,%3};"
        : "+f"(d[0]), "+f"(d[1]), "+f"(d[2]), "+f"(d[3])
        : "r"(a[0]), "r"(a[1]), "r"(a[2]), "r"(a[3]), "r"(b[0]), "r"(b[1]));
}
__device__ __forceinline__ uint32_t pack_hf(float a, float b) {
    __half2 t = __floats2half2_rn(a, b);
    return *(uint32_t*)&t;
}
__device__ __forceinline__ void cpa16(uint32_t dst, const void* src) {
    asm volatile("cp.async.cg.shared.global [%0], [%1], 16;" :: "r"(dst), "l"(src));
}

// ---------------- conversion kernels ----------------
__global__ __launch_bounds__(256) void conv4_kernel(const float* __restrict__ in,
                                                    __half* __restrict__ outh) {
    int i = blockIdx.x * 256 + threadIdx.x;
    float4 v = ((const float4*)in)[i];
    ((uint32_t*)outh)[2*i]   = pack_hf(v.x, v.y);
    ((uint32_t*)outh)[2*i+1] = pack_hf(v.z, v.w);
}

// in [K][N] fp32 -> out [N][K] fp16 (tiled transpose)
__global__ __launch_bounds__(256) void convT_kernel(const float* __restrict__ in,
                                                    __half* __restrict__ outT,
                                                    int K, int N) {
    __shared__ float t[32][33];
    int n0 = blockIdx.x * 32, k0 = blockIdx.y * 32;
    int tx = threadIdx.x, ty = threadIdx.y;   // block (32,8)
#pragma unroll
    for (int j = 0; j < 4; j++)
        t[ty + j*8][tx] = in[(size_t)(k0 + ty + j*8) * N + n0 + tx];
    __syncthreads();
#pragma unroll
    for (int j = 0; j < 4; j++) {
        int nl = ty + j*8;
        outT[(size_t)(n0 + nl) * K + k0 + tx] = __float2half(t[tx][nl]);
    }
}

// ---------------- fp16 GEMM: 256x128 tile, BK=32, double-buffered ----------------
#define LDSB    80
#define A_T     20480                  // 256 rows * 80
#define B_T     10240                  // 128 rows * 80
#define STAGE_B (A_T + B_T)            // 30720 : A|B
#define MM_SMEM (2*STAGE_B)            // 61440

template<int NR>
__device__ __forceinline__ void cpa_rows(uint32_t dst, const __half* __restrict__ g,
                                         int ld, int row0, int k0, int tid) {
#pragma unroll
    for (int l = 0; l < NR/64; l++) {
        int idx = tid + l * 256;
        int r   = idx >> 2;
        int seg = idx & 3;
        cpa16(dst + r*LDSB + seg*16, g + (size_t)(row0 + r) * ld + k0 + seg*8);
    }
}

__device__ __forceinline__ void gemm1_body(const __half* __restrict__ A,
                                           const __half* __restrict__ B,
                                           float* __restrict__ C, int N, int K) {
    extern __shared__ __align__(128) char smem[];
    const uint32_t sb = smem_u32(smem);
    const int tid  = threadIdx.x;
    const int wid  = tid >> 5;
    const int lane = tid & 31;
    const int wm   = wid >> 1;            // 0..3 -> 64-row slice
    const int wn   = wid & 1;             // 0..1 -> 64-col slice
    const int m0   = blockIdx.y * 256;
    const int n0   = blockIdx.x * 128;

    float acc[4][8][4];
#pragma unroll
    for (int mf = 0; mf < 4; mf++)
#pragma unroll
        for (int nf = 0; nf < 8; nf++)
#pragma unroll
            for (int c = 0; c < 4; c++) acc[mf][nf][c] = 0.f;

    const uint32_t aoff = (lane & 15) * LDSB + (lane >> 4) * 16;
    const uint32_t boff = ((lane & 7) + ((lane >> 4) << 3)) * LDSB + (((lane >> 3) & 1) * 16);

    const int NIT = K / 32;

    cpa_rows<256>(sb,         A, K, m0, 0, tid);
    cpa_rows<128>(sb + A_T,   B, K, n0, 0, tid);
    asm volatile("cp.async.commit_group;" ::: "memory");

    for (int it = 0; it < NIT; it++) {
        if (it + 1 < NIT) {
            const uint32_t nb = sb + ((it + 1) & 1) * STAGE_B;
            const int k2 = (it + 1) * 32;
            cpa_rows<256>(nb,       A, K, m0, k2, tid);
            cpa_rows<128>(nb + A_T, B, K, n0, k2, tid);
            asm volatile("cp.async.commit_group;" ::: "memory");
            asm volatile("cp.async.wait_group 1;" ::: "memory");
        } else {
            asm volatile("cp.async.wait_group 0;" ::: "memory");
        }
        __syncthreads();

        const uint32_t cbs = sb + (it & 1) * STAGE_B;
#pragma unroll
        for (int ks = 0; ks < 2; ks++) {
            const uint32_t kb = ks * 32;
            uint32_t ar[4][4];
#pragma unroll
            for (int mf = 0; mf < 4; mf++)
                ldsm_x4(ar[mf], cbs + (wm*64 + mf*16) * LDSB + aoff + kb);
#pragma unroll
            for (int nc = 0; nc < 4; nc++) {
                uint32_t br[4];
                ldsm_x4(br, cbs + A_T + (wn*64 + nc*16) * LDSB + boff + kb);
#pragma unroll
                for (int mf = 0; mf < 4; mf++) {
                    mma_f16(acc[mf][nc*2],   ar[mf], br);
                    mma_f16(acc[mf][nc*2+1], ar[mf], br + 2);
                }
            }
        }
        __syncthreads();
    }

    const int r0 = m0 + wm * 64 + (lane >> 2);
    const int c0 = n0 + wn * 64 + (lane & 3) * 2;
#pragma unroll
    for (int mf = 0; mf < 4; mf++)
#pragma unroll
        for (int nf = 0; nf < 8; nf++) {
            const float* a = acc[mf][nf];
            const int r = r0 + mf * 16;
            const int c = c0 + nf * 8;
            *(float2*)&C[(size_t)r * N + c]       = make_float2(a[0], a[1]);
            *(float2*)&C[(size_t)(r + 8) * N + c] = make_float2(a[2], a[3]);
        }
}

__global__ __launch_bounds__(256) void qkv_mma_kernel() {
    gemm1_body(g_x, g_Wq, g_qkv, QKVN, EMB);
}
__global__ __launch_bounds__(256) void out_mma_kernel(float* __restrict__ out) {
    gemm1_body(g_a, g_Wo, out, EMB, EMB);
}

// ---------------- RoPE cos/sin table ----------------
__global__ __launch_bounds__(256) void rot_kernel() {
    int idx = blockIdx.x * 256 + threadIdx.x;   // SEQ*32
    int s = idx >> 5, i = idx & 31;
    float freq = powf(10000.f, -(float)(2*i) / 64.f);
    float sv, cv;
    sincosf((float)s * freq, &sv, &cv);
    g_rot[idx] = make_float2(cv, sv);
}

// ---------------- prep: rope + fp16 ops for attention ----------------
// block = 256 threads, 64 s-rows of one (b,h)
__global__ __launch_bounds__(256) void qkv_prep_kernel() {
    __shared__ float vt[64][65];
    const int tid = threadIdx.x;
    const int s0  = blockIdx.x * 64;
    const int bh  = blockIdx.y;
    const int b   = bh >> 4, h = bh & 15;
    const size_t inb = (size_t)b * SEQ * QKVN + h * HD;
    const size_t qkb = (size_t)bh * SEQ * HD;

    // q: rope + scale; k: rope
#pragma unroll
    for (int which = 0; which < 2; which++) {
        __half* dst = which ? g_k : g_q;
        const float sc = which ? 1.f : 0.125f;
#pragma unroll
        for (int l = 0; l < 4; l++) {
            int idx = tid + l * 256;
            int s   = s0 + (idx >> 4);
            int f4  = idx & 15;
            float4 v = *(const float4*)&g_qkv[inb + (size_t)s * QKVN + which*EMB + f4*4];
            float2 cs0 = g_rot[s*32 + f4*2];
            float2 cs1 = g_rot[s*32 + f4*2 + 1];
            float o0 = (v.x * cs0.x - v.y * cs0.y) * sc;
            float o1 = (v.x * cs0.y + v.y * cs0.x) * sc;
            float o2 = (v.z * cs1.x - v.w * cs1.y) * sc;
            float o3 = (v.z * cs1.y + v.w * cs1.x) * sc;
            size_t o = qkb + (size_t)s * HD + f4 * 4;
            uint2 ph;
            ph.x = pack_hf(o0, o1); ph.y = pack_hf(o2, o3);
            *(uint2*)&dst[o] = ph;
        }
    }
    // v: transpose to [d][s]
#pragma unroll
    for (int l = 0; l < 4; l++) {
        int idx = tid + l * 256;
        int sl  = idx >> 4;
        int f4  = idx & 15;
        float4 v = *(const float4*)&g_qkv[inb + (size_t)(s0 + sl) * QKVN + 2*EMB + f4*4];
        vt[f4*4+0][sl] = v.x;
        vt[f4*4+1][sl] = v.y;
        vt[f4*4+2][sl] = v.z;
        vt[f4*4+3][sl] = v.w;
    }
    __syncthreads();
#pragma unroll
    for (int l = 0; l < 4; l++) {
        int idx = tid + l * 256;
        int d   = idx >> 4;
        int sc  = (idx & 15) * 4;
        size_t o = ((size_t)bh * HD + d) * SEQ + s0 + sc;
        uint2 ph;
        ph.x = pack_hf(vt[d][sc],   vt[d][sc+1]);
        ph.y = pack_hf(vt[d][sc+2], vt[d][sc+3]);
        *(uint2*)&g_v[o] = ph;
    }
}

// ---------------- fp16 tensor-core flash attention (single-term) ----------------
#define AQS    144                      // smem row stride bytes
#define SQ_O   0
#define SSTG   18432                    // stages start
#define STG_B  18432                    // K|V per stage
#define SK_O   0
#define SV_O   9216
#define ATT_SMEM (SSTG + 2*STG_B)       // 55296

__device__ __forceinline__ void attn_kv_load(uint32_t sbase, size_t qk, size_t vb,
                                             int kt, int tid) {
#pragma unroll
    for (int l = 0; l < 4; l++) {
        int idx = tid + l * 256;        // 0..1023
        int mat = idx >> 9;             // 0:K 1:V (warp-uniform)
        int r   = (idx >> 3) & 63;
        int c   = idx & 7;
        if (mat == 0)
            cpa16(sbase + SK_O + r*AQS + c*16, g_k + qk + (size_t)(kt*64 + r)*HD + c*8);
        else
            cpa16(sbase + SV_O + r*AQS + c*16, g_v + vb + (size_t)r*SEQ + kt*64 + c*8);
    }
}

__global__ __launch_bounds__(256, 2) void attn_mma_kernel() {
    extern __shared__ __align__(128) char sm[];
    const uint32_t sb = smem_u32(sm);
    const int tid  = threadIdx.x;
    const int w    = tid >> 5;
    const int lane = tid & 31;
    const int qt   = 15 - (int)blockIdx.y;      // heavy tiles first
    const int bh   = blockIdx.z;
    const int qbase = qt * 128;
    const size_t qk = (size_t)bh * SEQ * HD;    // q/k [s][d] base
    const size_t vb = (size_t)bh * HD * SEQ;    // v [d][s] base

    // Q tile via cp.async
#pragma unroll
    for (int l = 0; l < 4; l++) {
        int idx = tid + l * 256;        // 0..1023
        int r   = idx >> 3;             // 0..127
        int c   = idx & 7;
        cpa16(sb + SQ_O + r*AQS + c*16, g_q + qk + (size_t)(qbase + r)*HD + c*8);
    }
    attn_kv_load(sb + SSTG, qk, vb, 0, tid);
    asm volatile("cp.async.commit_group;" ::: "memory");

    const uint32_t aoff = (lane & 15) * AQS + (lane >> 4) * 16;
    const uint32_t boff = ((lane & 7) + ((lane >> 4) << 3)) * AQS + ((lane >> 3) & 1) * 16;
    const int r0 = qbase + w * 16;

    float o[8][4];
#pragma unroll
    for (int t = 0; t < 8; t++)
#pragma unroll
        for (int c = 0; c < 4; c++) o[t][c] = 0.f;
    float m0r = -1e30f, m1r = -1e30f, l0r = 0.f, l1r = 0.f;

    const int nkt = 2 * qt + 2;
    for (int kt = 0; kt < nkt; kt++) {
        if (kt + 1 < nkt) {
            attn_kv_load(sb + SSTG + ((kt + 1) & 1) * STG_B, qk, vb, kt + 1, tid);
            asm volatile("cp.async.commit_group;" ::: "memory");
            asm volatile("cp.async.wait_group 1;" ::: "memory");
        } else {
            asm volatile("cp.async.wait_group 0;" ::: "memory");
        }
        __syncthreads();

        const uint32_t stg = sb + SSTG + (kt & 1) * STG_B;

        if (kt * 64 <= r0 + 15) {    // tile not fully masked for this warp
            // ---- S = Q K^T ----
            float st[8][4];
#pragma unroll
            for (int t = 0; t < 8; t++)
#pragma unroll
                for (int c = 0; c < 4; c++) st[t][c] = 0.f;

#pragma unroll
            for (int j = 0; j < 4; j++) {
                uint32_t qr[4];
                ldsm_x4(qr, sb + SQ_O + w*16*AQS + aoff + j*32);
#pragma unroll
                for (int nb = 0; nb < 4; nb++) {
                    uint32_t kr[4];
                    ldsm_x4(kr, stg + SK_O + nb*16*AQS + boff + j*32);
                    mma_f16(st[2*nb],   qr, kr);
                    mma_f16(st[2*nb+1], qr, kr + 2);
                }
            }

            // ---- causal mask ----
            const int rq0 = r0 + (lane >> 2);
            if (kt * 64 + 63 > r0) {
#pragma unroll
                for (int t = 0; t < 8; t++) {
                    int c = kt*64 + t*8 + (lane & 3)*2;
                    if (c     > rq0)     st[t][0] = -1e30f;
                    if (c + 1 > rq0)     st[t][1] = -1e30f;
                    if (c     > rq0 + 8) st[t][2] = -1e30f;
                    if (c + 1 > rq0 + 8) st[t][3] = -1e30f;
                }
            }

            // ---- online softmax ----
            float rm0 = -1e30f, rm1 = -1e30f;
#pragma unroll
            for (int t = 0; t < 8; t++) {
                rm0 = fmaxf(rm0, fmaxf(st[t][0], st[t][1]));
                rm1 = fmaxf(rm1, fmaxf(st[t][2], st[t][3]));
            }
            rm0 = fmaxf(rm0, __shfl_xor_sync(0xffffffffu, rm0, 1));
            rm0 = fmaxf(rm0, __shfl_xor_sync(0xffffffffu, rm0, 2));
            rm1 = fmaxf(rm1, __shfl_xor_sync(0xffffffffu, rm1, 1));
            rm1 = fmaxf(rm1, __shfl_xor_sync(0xffffffffu, rm1, 2));
            float mn0 = fmaxf(m0r, rm0), mn1 = fmaxf(m1r, rm1);
            float al0 = __expf(m0r - mn0), al1 = __expf(m1r - mn1);
            float rs0 = 0.f, rs1 = 0.f;
#pragma unroll
            for (int t = 0; t < 8; t++) {
                st[t][0] = __expf(st[t][0] - mn0);
                st[t][1] = __expf(st[t][1] - mn0);
                st[t][2] = __expf(st[t][2] - mn1);
                st[t][3] = __expf(st[t][3] - mn1);
                rs0 += st[t][0] + st[t][1];
                rs1 += st[t][2] + st[t][3];
            }
            rs0 += __shfl_xor_sync(0xffffffffu, rs0, 1);
            rs0 += __shfl_xor_sync(0xffffffffu, rs0, 2);
            rs1 += __shfl_xor_sync(0xffffffffu, rs1, 1);
            rs1 += __shfl_xor_sync(0xffffffffu, rs1, 2);
            l0r = l0r * al0 + rs0;
            l1r = l1r * al1 + rs1;
            m0r = mn0; m1r = mn1;
#pragma unroll
            for (int t = 0; t < 8; t++) {
                o[t][0] *= al0; o[t][1] *= al0;
                o[t][2] *= al1; o[t][3] *= al1;
            }

            // ---- O += P V ----
#pragma unroll
            for (int j = 0; j < 4; j++) {
                uint32_t ph[4];
                ph[0] = pack_hf(st[2*j][0],   st[2*j][1]);
                ph[1] = pack_hf(st[2*j][2],   st[2*j][3]);
                ph[2] = pack_hf(st[2*j+1][0], st[2*j+1][1]);
                ph[3] = pack_hf(st[2*j+1][2], st[2*j+1][3]);
#pragma unroll
                for (int db = 0; db < 4; db++) {
                    uint32_t vr[4];
                    ldsm_x4(vr, stg + SV_O + db*16*AQS + boff + j*32);
                    mma_f16(o[2*db],   ph, vr);
                    mma_f16(o[2*db+1], ph, vr + 2);
                }
            }
        }
        __syncthreads();
    }

    // ---- epilogue: normalize, fp16, write g_a ----
    const int b = bh >> 4, h = bh & 15;
    const float inv0 = 1.f / l0r, inv1 = 1.f / l1r;
    const int rq0 = qbase + w*16 + (lane >> 2);
#pragma unroll
    for (int t = 0; t < 8; t++) {
        int col = h * HD + t*8 + (lane & 3) * 2;
        size_t i0 = ((size_t)b*SEQ + rq0)     * EMB + col;
        size_t i1 = ((size_t)b*SEQ + rq0 + 8) * EMB + col;
        *(uint32_t*)&g_a[i0] = pack_hf(o[t][0] * inv0, o[t][1] * inv0);
        *(uint32_t*)&g_a[i1] = pack_hf(o[t][2] * inv1, o[t][3] * inv1);
    }
}

// ---------------- launch ----------------
extern "C" void kernel_launch(void* const* d_in, const int* in_sizes, int n_in,
                              void* d_out, int out_size) {
    const float* x    = (const float*)d_in[0];
    const float* Wqkv = (const float*)d_in[1];
    const float* Wout = (const float*)d_in[2];
    float* out = (float*)d_out;

    cudaFuncSetAttribute(attn_mma_kernel, cudaFuncAttributeMaxDynamicSharedMemorySize, ATT_SMEM);
    cudaFuncSetAttribute(qkv_mma_kernel,  cudaFuncAttributeMaxDynamicSharedMemorySize, MM_SMEM);
    cudaFuncSetAttribute(out_mma_kernel,  cudaFuncAttributeMaxDynamicSharedMemorySize, MM_SMEM);

    __half *p_x, *p_Wq, *p_Wo;
    cudaGetSymbolAddress((void**)&p_x,  g_x);
    cudaGetSymbolAddress((void**)&p_Wq, g_Wq);
    cudaGetSymbolAddress((void**)&p_Wo, g_Wo);

    // x fp16, Wqkv^T fp16
    conv4_kernel<<<(ROWS*EMB)/4/256, 256>>>(x, p_x);
    convT_kernel<<<dim3(QKVN/32, EMB/32), dim3(32,8)>>>(Wqkv, p_Wq, EMB, QKVN);
    // QKV projection
    qkv_mma_kernel<<<dim3(QKVN/128, ROWS/256), 256, MM_SMEM>>>();
    // RoPE table + prep
    rot_kernel<<<(SEQ*32)/256, 256>>>();
    qkv_prep_kernel<<<dim3(SEQ/64, BATCH*NH), 256>>>();
    // flash attention
    attn_mma_kernel<<<dim3(1, SEQ/128, BATCH*NH), 256, ATT_SMEM>>>();
    // output projection
    convT_kernel<<<dim3(EMB/32, EMB/32), dim3(32,8)>>>(Wout, p_Wo, EMB, EMB);
    out_mma_kernel<<<dim3(EMB/128, ROWS/256), 256, MM_SMEM>>>(out);
}